// round 9
// baseline (speedup 1.0000x reference)
#include <cuda_runtime.h>
#include <cstdint>

// ---------------- problem constants ----------------
#define HD   256      // hidden / embedding dim
#define G3   768      // 3*H gate dim
#define VOCAB 30000
#define NW   2048     // word-level sequences (B*R*S)
#define TW   32       // word-level timesteps (W)
#define NS   128      // sentence-level sequences (B*R)
#define TS   16       // sentence-level timesteps (S)
#define NR   8        // review-level sequences (B)
#define TR   16       // review-level timesteps (R)

#define SP   36       // gemm smem row stride (mod 32 == 4; 16B-aligned)
#define WSP  260      // resident-W row stride (mod 32 == 4; 16B-aligned)
#define HSP  20       // scan H-chunk row stride (16 data + 4 pad; 16B-aligned)

// scan smem: Wres[48*WSP] + Hsm[3][256][HSP]
#define SCAN_SMEM_WORDS (48*WSP + 3*256*HSP)
#define SCAN_SMEM_BYTES (SCAN_SMEM_WORDS * 4)
// gemm smem: double-buffered As[2][128][SP] + Bs[2][64][SP]
#define GEMM_SMEM_WORDS (2*128*SP + 2*64*SP)
#define GEMM_SMEM_BYTES (GEMM_SMEM_WORDS * 4)

#define NBAR 20       // word 0..15, sentence 16..17, review 18..19
#define BPAD 32       // barrier slot padding (128B)

// ---------------- scratch (static device globals; no runtime alloc) ----------------
__device__ float g_PV [(size_t)2*VOCAB*G3];        // projected vocab per dir
__device__ float g_GXs[(size_t)2*NS*TS*G3];        // sentence-level gx
__device__ float g_GXr[(size_t)2*NR*TR*G3];        // review-level gx
__device__ float g_Hw [2][(size_t)2*NW*HD];        // ping-pong hidden, word
__device__ float g_Hs [2][(size_t)2*NS*HD];        // sentence
__device__ float g_Hr [2][(size_t)2*NR*HD];        // review

// grid-barrier state: one padded slot per (scan, dir, rowgroup)
__device__ unsigned g_cnt[NBAR * BPAD];
__device__ volatile unsigned g_phase[NBAR * BPAD];

// ---------------- helpers ----------------
__device__ __forceinline__ float fsigm(float x) {
    float e = __expf(-x);
    return __fdividef(1.f, 1.f + e);
}
__device__ __forceinline__ float ftanh(float x) {
    float ax = fabsf(x);
    float e = __expf(-2.f * ax);
    float r = __fdividef(1.f - e, 1.f + e);
    return copysignf(r, x);
}

__device__ __forceinline__ unsigned f2tf(float x) {
    unsigned u;
    asm("cvt.rna.tf32.f32 %0, %1;" : "=r"(u) : "f"(x));
    return u;
}

__device__ __forceinline__ void mma8(float* d,
                                     unsigned a0, unsigned a1, unsigned a2, unsigned a3,
                                     unsigned b0, unsigned b1) {
    asm volatile(
        "mma.sync.aligned.m16n8k8.row.col.f32.tf32.tf32.f32 "
        "{%0,%1,%2,%3},{%4,%5,%6,%7},{%8,%9},{%0,%1,%2,%3};"
        : "+f"(d[0]), "+f"(d[1]), "+f"(d[2]), "+f"(d[3])
        : "r"(a0), "r"(a1), "r"(a2), "r"(a3), "r"(b0), "r"(b1));
}

__device__ __forceinline__ void ldsm4(unsigned& r0, unsigned& r1, unsigned& r2, unsigned& r3,
                                      unsigned addr) {
    asm volatile("ldmatrix.sync.aligned.m8n8.x4.shared.b16 {%0,%1,%2,%3}, [%4];"
                 : "=r"(r0), "=r"(r1), "=r"(r2), "=r"(r3) : "r"(addr));
}
__device__ __forceinline__ void ldsm2(unsigned& r0, unsigned& r1, unsigned addr) {
    asm volatile("ldmatrix.sync.aligned.m8n8.x2.shared.b16 {%0,%1}, [%2];"
                 : "=r"(r0), "=r"(r1) : "r"(addr));
}

__device__ __forceinline__ void cpa16(unsigned dst, const void* src, unsigned bytes) {
    asm volatile("cp.async.ca.shared.global [%0], [%1], 16, %2;"
                 :: "r"(dst), "l"(src), "r"(bytes));
}
__device__ __forceinline__ void cpa_commit() {
    asm volatile("cp.async.commit_group;" ::: "memory");
}

__global__ void kinit_bar() {
    int i = threadIdx.x;
    if (i < NBAR * BPAD) { g_cnt[i] = 0; g_phase[i] = 0; }
}

// software grid barrier over an nCTA-member group (slot = id*BPAD)
__device__ __forceinline__ void gbar(int id, unsigned nCTA, unsigned target) {
    __syncthreads();
    if (threadIdx.x == 0) {
        __threadfence();
        unsigned* cnt = &g_cnt[id * BPAD];
        unsigned old = atomicAdd(cnt, 1u);
        if (old == nCTA - 1u) {
            *cnt = 0u;
            __threadfence();
            g_phase[id * BPAD] = target;
        } else {
            while (g_phase[id * BPAD] < target) __nanosleep(64);
        }
        __threadfence();
    }
    __syncthreads();
}

// ---------------- TF32 GEMM: C[d][M,768] = (A(+A2))[M,256] @ W[d][768,256]^T + bias[d] ----------------
__global__ __launch_bounds__(256, 2)
void gemm_proj_mma(const float* __restrict__ A, const float* __restrict__ A2, int M,
                   const float* __restrict__ W, const float* __restrict__ bias,
                   float* __restrict__ C)
{
    extern __shared__ unsigned gsm[];
    unsigned* As = gsm;                  // [2][128][SP]
    unsigned* Bs = gsm + 2 * 128 * SP;   // [2][64][SP]

    int d = blockIdx.z;
    const float* Wd = W    + (size_t)d * G3 * HD;
    const float* bd = bias + (size_t)d * G3;
    float*       Cd = C    + (size_t)d * M * G3;

    int m0 = blockIdx.x * 128;
    int n0 = blockIdx.y * 64;

    int tid = threadIdx.x, lane = tid & 31, wid = tid >> 5;
    int wm = wid & 3, wn = wid >> 2;
    int RB = wm * 32, CB = wn * 32;
    int g = lane >> 2, c = lane & 3;

    int l7 = lane & 7, ts = lane >> 3;
    int a_row_off = l7 + (ts & 1) * 8;
    int a_col_off = (ts >> 1) * 4;
    unsigned sAs = (unsigned)__cvta_generic_to_shared(As);
    unsigned sBs = (unsigned)__cvta_generic_to_shared(Bs);

    unsigned aAddr[2], bAddr[2];
#pragma unroll
    for (int mt = 0; mt < 2; ++mt)
        aAddr[mt] = sAs + (unsigned)(((RB + mt * 16 + a_row_off) * SP + a_col_off) * 4);
    int ntl = ts >> 1, bcol = (ts & 1) * 4;
#pragma unroll
    for (int p = 0; p < 2; ++p)
        bAddr[p] = sBs + (unsigned)(((CB + (2 * p + ntl) * 8 + l7) * SP + bcol) * 4);

    float acc[2][4][4];
#pragma unroll
    for (int i = 0; i < 2; ++i)
#pragma unroll
        for (int j = 0; j < 4; ++j)
#pragma unroll
            for (int k = 0; k < 4; ++k) acc[i][j][k] = 0.f;

    int lr = tid >> 3, lq = tid & 7;

    float4 pa[4], pw[2];
#pragma unroll
    for (int it = 0; it < 4; ++it) {
        int r = lr + it * 32;
        pa[it] = make_float4(0.f, 0.f, 0.f, 0.f);
        if (m0 + r < M) {
            size_t off = (size_t)(m0 + r) * HD + lq * 4;
            pa[it] = *(const float4*)(A + off);
            if (A2) {
                float4 b = *(const float4*)(A2 + off);
                pa[it].x += b.x; pa[it].y += b.y; pa[it].z += b.z; pa[it].w += b.w;
            }
        }
    }
#pragma unroll
    for (int it = 0; it < 2; ++it) {
        int r = lr + it * 32;
        pw[it] = *(const float4*)(Wd + (size_t)(n0 + r) * HD + lq * 4);
    }
#pragma unroll
    for (int it = 0; it < 4; ++it) {
        int r = lr + it * 32;
        *(uint4*)(As + (size_t)r * SP + lq * 4) =
            make_uint4(f2tf(pa[it].x), f2tf(pa[it].y), f2tf(pa[it].z), f2tf(pa[it].w));
    }
#pragma unroll
    for (int it = 0; it < 2; ++it) {
        int r = lr + it * 32;
        *(uint4*)(Bs + (size_t)r * SP + lq * 4) =
            make_uint4(f2tf(pw[it].x), f2tf(pw[it].y), f2tf(pw[it].z), f2tf(pw[it].w));
    }
    __syncthreads();

    for (int k0i = 0; k0i < 8; ++k0i) {
        int cur = k0i & 1;
        if (k0i < 7) {
            int k0 = (k0i + 1) * 32;
#pragma unroll
            for (int it = 0; it < 4; ++it) {
                int r = lr + it * 32;
                pa[it] = make_float4(0.f, 0.f, 0.f, 0.f);
                if (m0 + r < M) {
                    size_t off = (size_t)(m0 + r) * HD + k0 + lq * 4;
                    pa[it] = *(const float4*)(A + off);
                    if (A2) {
                        float4 b = *(const float4*)(A2 + off);
                        pa[it].x += b.x; pa[it].y += b.y; pa[it].z += b.z; pa[it].w += b.w;
                    }
                }
            }
#pragma unroll
            for (int it = 0; it < 2; ++it) {
                int r = lr + it * 32;
                pw[it] = *(const float4*)(Wd + (size_t)(n0 + r) * HD + k0 + lq * 4);
            }
        }

        unsigned aBuf = (unsigned)(cur * 128 * SP * 4);
        unsigned bBuf = (unsigned)(cur * 64 * SP * 4);
#pragma unroll
        for (int ks = 0; ks < 4; ++ks) {
            unsigned kbo = (unsigned)(ks * 32);
            unsigned a[2][4];
#pragma unroll
            for (int mt = 0; mt < 2; ++mt)
                ldsm4(a[mt][0], a[mt][1], a[mt][2], a[mt][3], aAddr[mt] + aBuf + kbo);
            unsigned b[4][2];
#pragma unroll
            for (int p = 0; p < 2; ++p)
                ldsm4(b[2*p][0], b[2*p][1], b[2*p+1][0], b[2*p+1][1], bAddr[p] + bBuf + kbo);
#pragma unroll
            for (int nt = 0; nt < 4; ++nt)
#pragma unroll
                for (int mt = 0; mt < 2; ++mt)
                    mma8(acc[mt][nt], a[mt][0], a[mt][1], a[mt][2], a[mt][3],
                         b[nt][0], b[nt][1]);
        }

        if (k0i < 7) {
            unsigned* An = As + (size_t)(cur ^ 1) * 128 * SP;
            unsigned* Bn = Bs + (size_t)(cur ^ 1) * 64 * SP;
#pragma unroll
            for (int it = 0; it < 4; ++it) {
                int r = lr + it * 32;
                *(uint4*)(An + (size_t)r * SP + lq * 4) =
                    make_uint4(f2tf(pa[it].x), f2tf(pa[it].y), f2tf(pa[it].z), f2tf(pa[it].w));
            }
#pragma unroll
            for (int it = 0; it < 2; ++it) {
                int r = lr + it * 32;
                *(uint4*)(Bn + (size_t)r * SP + lq * 4) =
                    make_uint4(f2tf(pw[it].x), f2tf(pw[it].y), f2tf(pw[it].z), f2tf(pw[it].w));
            }
        }
        __syncthreads();
    }

#pragma unroll
    for (int nt = 0; nt < 4; ++nt) {
        int col = n0 + CB + nt * 8 + 2 * c;
        float2 bb = *(const float2*)(bd + col);
#pragma unroll
        for (int mt = 0; mt < 2; ++mt) {
            int row0 = m0 + RB + mt * 16 + g;
            if (row0 < M) {
                float2 o = make_float2(acc[mt][nt][0] + bb.x, acc[mt][nt][1] + bb.y);
                *(float2*)(Cd + (size_t)row0 * G3 + col) = o;
            }
            int row1 = row0 + 8;
            if (row1 < M) {
                float2 o = make_float2(acc[mt][nt][2] + bb.x, acc[mt][nt][3] + bb.y);
                *(float2*)(Cd + (size_t)row1 * G3 + col) = o;
            }
        }
    }
}

// ---------------- persistent fused GRU scan ----------------
// CTA: 256 rows x 16 j-cols x 3 gates; W resident in smem; 2 CTAs/SM.
// H staged via cp.async 3-stage pipeline (16-k chunks). Per-(dir, rowgroup)
// barrier (16 CTAs); skipped on the final step.
__global__ __launch_bounds__(256, 2)
void gru_scan(float* __restrict__ H0, float* __restrict__ H1,
              const float* __restrict__ Whh,   // [2][768][256]
              const float* __restrict__ bhh,   // [2][768]
              const float* __restrict__ GX,    // [2][N*T][768] or nullptr
              const float* __restrict__ PV,    // [2][VOCAB][768] or nullptr
              const int*   __restrict__ tok,   // tokens or nullptr
              int N, int T, int barBase)
{
    extern __shared__ unsigned smem[];
    unsigned* Wres = smem;                       // [48][WSP]
    unsigned* Hsm  = smem + 48 * WSP;            // [3][256][HSP]

    int d  = blockIdx.z;
    int n0 = blockIdx.x * 256;
    int j0 = blockIdx.y * 16;
    int bid = barBase + d * gridDim.x + blockIdx.x;

    const float* Wd = Whh + (size_t)d * G3 * HD;

    int tid = threadIdx.x, lane = tid & 31, wid = tid >> 5;
    int wm = wid & 3, wn = wid >> 2;
    int RB = wm * 64, CB = wn * 8;
    int g = lane >> 2, c = lane & 3;

    // ---- load resident W slice (RNA-converted once) ----
    for (int idx = tid; idx < 48 * 64; idx += 256) {
        int row = idx >> 6;
        int c4  = idx & 63;
        int gt = row >> 4, j = row & 15;
        float4 v = *(const float4*)(Wd + (size_t)(gt * 256 + j0 + j) * HD + c4 * 4);
        *(uint4*)(Wres + (size_t)row * WSP + c4 * 4) =
            make_uint4(f2tf(v.x), f2tf(v.y), f2tf(v.z), f2tf(v.w));
    }
    __syncthreads();

    int l7 = lane & 7, ts = lane >> 3;
    int a_row_off = l7 + (ts & 1) * 8;
    int a_col_off = (ts >> 1) * 4;
    unsigned sH = (unsigned)__cvta_generic_to_shared(Hsm);
    unsigned sW = (unsigned)__cvta_generic_to_shared(Wres);

    unsigned aAddr0[4];
#pragma unroll
    for (int mt = 0; mt < 4; ++mt)
        aAddr0[mt] = sH + (unsigned)(((RB + mt * 16 + a_row_off) * HSP + a_col_off) * 4);
    unsigned bAddr01 = sW + (unsigned)((((ts >> 1) * 16 + CB + l7) * WSP + (ts & 1) * 4) * 4);
    unsigned bAddr2  = sW + (unsigned)(((32 + CB + l7) * WSP + ((ts & 1) * 4)) * 4);

    // cp.async loader roles: 4 granules of 16B per chunk
    int cp_row = tid >> 2;            // 0..63 base, +64 per it? no: granule index
    int cp_qc  = tid & 3;
    // granule g = tid + it*256 -> row = g>>2 (0..255), qc = g&3

    bool is64 = false;
    if (tok) is64 = (tok[1] == 0) & (tok[3] == 0) & (tok[5] == 0) & (tok[7] == 0);

    int cc = j0 + CB + 2 * c;
    float2 br2 = *(const float2*)(bhh + (size_t)d * G3 + cc);
    float2 bz2 = *(const float2*)(bhh + (size_t)d * G3 + 256 + cc);
    float2 bn2 = *(const float2*)(bhh + (size_t)d * G3 + 512 + cc);

    // this thread's 8 row instances
    int rowi[8];
#pragma unroll
    for (int idx = 0; idx < 8; ++idx) {
        int mt = idx >> 1, half = idx & 1;
        rowi[idx] = n0 + RB + mt * 16 + g + half * 8;
    }

    for (int t = 0; t < T; ++t) {
        const float* Hin  = (t & 1) ? H1 : H0;
        float*       Hout = (t & 1) ? H0 : H1;
        int teff = d ? (T - 1 - t) : t;

        // gx row pointers for this step
        const float* gxp[8];
#pragma unroll
        for (int idx = 0; idx < 8; ++idx) {
            int r = rowi[idx];
            if (r < N) {
                if (tok) {
                    int ti = r * T + teff;
                    int tv = is64 ? tok[2 * (size_t)ti] : tok[ti];
                    gxp[idx] = PV + ((size_t)d * VOCAB + tv) * G3;
                } else {
                    gxp[idx] = GX + ((size_t)d * N * T + (size_t)r * T + teff) * G3;
                }
            } else gxp[idx] = PV ? PV : GX;
        }

        float acc[3][4][4];
#pragma unroll
        for (int i = 0; i < 3; ++i)
#pragma unroll
            for (int j = 0; j < 4; ++j)
#pragma unroll
                for (int k = 0; k < 4; ++k) acc[i][j][k] = 0.f;

        if (t > 0) {   // step 0: Hin == 0 -> Gh == 0, skip MMA entirely
            const float* Hbase = Hin + (size_t)d * N * HD;

            // prologue: issue chunks 0 and 1
#pragma unroll
            for (int pc = 0; pc < 2; ++pc) {
#pragma unroll
                for (int it = 0; it < 4; ++it) {
                    int gr = (tid + it * 256);
                    int row = gr >> 2, qc = gr & 3;
                    int rclamp = (n0 + row < N) ? (n0 + row) : (N - 1);
                    unsigned bytes = (n0 + row < N) ? 16u : 0u;
                    unsigned dst = sH + (unsigned)(((pc * 256 + row) * HSP + qc * 4) * 4);
                    cpa16(dst, Hbase + (size_t)rclamp * HD + pc * 16 + qc * 4, bytes);
                }
                cpa_commit();
            }

#pragma unroll
            for (int ci = 0; ci < 16; ++ci) {
                if (ci < 15) asm volatile("cp.async.wait_group 1;" ::: "memory");
                else         asm volatile("cp.async.wait_group 0;" ::: "memory");
                __syncthreads();

                if (ci < 14) {
                    int nc = ci + 2, nb = nc % 3;
#pragma unroll
                    for (int it = 0; it < 4; ++it) {
                        int gr = (tid + it * 256);
                        int row = gr >> 2, qc = gr & 3;
                        int rclamp = (n0 + row < N) ? (n0 + row) : (N - 1);
                        unsigned bytes = (n0 + row < N) ? 16u : 0u;
                        unsigned dst = sH + (unsigned)(((nb * 256 + row) * HSP + qc * 4) * 4);
                        cpa16(dst, Hbase + (size_t)rclamp * HD + nc * 16 + qc * 4, bytes);
                    }
                    cpa_commit();
                }

                unsigned bufB = (unsigned)((ci % 3) * 256 * HSP * 4);
                unsigned kwoW = (unsigned)(ci * 64);
#pragma unroll
                for (int ks = 0; ks < 2; ++ks) {
                    unsigned kbo = (unsigned)(ks * 32);
                    unsigned a[4][4];
#pragma unroll
                    for (int mt = 0; mt < 4; ++mt)
                        ldsm4(a[mt][0], a[mt][1], a[mt][2], a[mt][3],
                              aAddr0[mt] + bufB + kbo);
                    unsigned b00, b01, b10, b11, b20, b21;
                    ldsm4(b00, b01, b10, b11, bAddr01 + kwoW + kbo);
                    ldsm2(b20, b21, bAddr2 + kwoW + kbo);
#pragma unroll
                    for (int mt = 0; mt < 4; ++mt) {
                        mma8(acc[0][mt], a[mt][0], a[mt][1], a[mt][2], a[mt][3], b00, b01);
                        mma8(acc[1][mt], a[mt][0], a[mt][1], a[mt][2], a[mt][3], b10, b11);
                        mma8(acc[2][mt], a[mt][0], a[mt][1], a[mt][2], a[mt][3], b20, b21);
                    }
                }
            }
        }

        // ---- gate math epilogue: 8 instances in 2 phases of 4 ----
#pragma unroll
        for (int phx = 0; phx < 2; ++phx) {
            float2 GR[4], GZ[4], GN[4], HH[4];
            bool val[4];
#pragma unroll
            for (int i = 0; i < 4; ++i) {
                int idx = phx * 4 + i;
                int r = rowi[idx];
                val[i] = (r < N);
                GR[i] = GZ[i] = GN[i] = HH[i] = make_float2(0.f, 0.f);
                if (val[i]) {
                    const float* gxrow = gxp[idx];
                    GR[i] = *(const float2*)(gxrow + cc);
                    GZ[i] = *(const float2*)(gxrow + 256 + cc);
                    GN[i] = *(const float2*)(gxrow + 512 + cc);
                    if (t > 0) HH[i] = *(const float2*)(Hin + (size_t)(d * N + r) * HD + cc);
                }
            }
#pragma unroll
            for (int i = 0; i < 4; ++i) {
                if (!val[i]) continue;
                int idx = phx * 4 + i;
                int mt = idx >> 1, half = idx & 1;
                float aR0 = acc[0][mt][half * 2 + 0], aR1 = acc[0][mt][half * 2 + 1];
                float aZ0 = acc[1][mt][half * 2 + 0], aZ1 = acc[1][mt][half * 2 + 1];
                float aN0 = acc[2][mt][half * 2 + 0], aN1 = acc[2][mt][half * 2 + 1];

                float r0 = fsigm(GR[i].x + aR0 + br2.x);
                float r1 = fsigm(GR[i].y + aR1 + br2.y);
                float z0 = fsigm(GZ[i].x + aZ0 + bz2.x);
                float z1 = fsigm(GZ[i].y + aZ1 + bz2.y);
                float n0v = ftanh(GN[i].x + r0 * (aN0 + bn2.x));
                float n1v = ftanh(GN[i].y + r1 * (aN1 + bn2.y));

                float2 o;
                o.x = n0v + z0 * (HH[i].x - n0v);
                o.y = n1v + z1 * (HH[i].y - n1v);
                *(float2*)(Hout + (size_t)(d * N + rowi[idx]) * HD + cc) = o;
            }
        }

        if (t + 1 < T) gbar(bid, 16, (unsigned)(t + 1));
    }
    (void)cp_row; (void)cp_qc;
}

// ---------------- FC head: Linear(256->128) -> SELU -> Linear(128->1) on (X+X2) ----------------
__global__ void fc_head(const float* __restrict__ X, const float* __restrict__ X2,
                        const float* __restrict__ W1, const float* __restrict__ b1,
                        const float* __restrict__ W2, const float* __restrict__ b2,
                        float* __restrict__ out)
{
    int row = blockIdx.x;
    int h = threadIdx.x;  // 128 threads
    const float* x  = X  + (size_t)row * HD;
    const float* x2 = X2 + (size_t)row * HD;
    const float* w  = W1 + (size_t)h * HD;
    float s = 0.f;
#pragma unroll 8
    for (int k = 0; k < HD; k += 4) {
        float4 xv = *(const float4*)(x + k);
        float4 yv = *(const float4*)(x2 + k);
        float4 wv = *(const float4*)(w + k);
        s += (xv.x + yv.x) * wv.x + (xv.y + yv.y) * wv.y
           + (xv.z + yv.z) * wv.z + (xv.w + yv.w) * wv.w;
    }
    s += b1[h];
    const float SC = 1.0507009873554805f, AL = 1.6732632423543772f;
    float selu = SC * (s > 0.f ? s : AL * expm1f(s));
    float v = selu * W2[h];
    __shared__ float red[128];
    red[h] = v; __syncthreads();
    for (int st = 64; st > 0; st >>= 1) {
        if (h < st) red[h] += red[h + st];
        __syncthreads();
    }
    if (h == 0) out[row] = red[0] + b2[0];
}

// ---------------- launch ----------------
extern "C" void kernel_launch(void* const* d_in, const int* in_sizes, int n_in,
                              void* d_out, int out_size)
{
    const int*   tok   = (const int*)  d_in[0];
    const float* emb   = (const float*)d_in[1];
    const float* wWih  = (const float*)d_in[2];
    const float* wWhh  = (const float*)d_in[3];
    const float* wbih  = (const float*)d_in[4];
    const float* wbhh  = (const float*)d_in[5];
    const float* sWih  = (const float*)d_in[6];
    const float* sWhh  = (const float*)d_in[7];
    const float* sbih  = (const float*)d_in[8];
    const float* sbhh  = (const float*)d_in[9];
    const float* rWih  = (const float*)d_in[10];
    const float* rWhh  = (const float*)d_in[11];
    const float* rbih  = (const float*)d_in[12];
    const float* rbhh  = (const float*)d_in[13];
    const float* rfcW1 = (const float*)d_in[14];
    const float* rfcb1 = (const float*)d_in[15];
    const float* rfcW2 = (const float*)d_in[16];
    const float* rfcb2 = (const float*)d_in[17];
    const float* pfcW1 = (const float*)d_in[18];
    const float* pfcb1 = (const float*)d_in[19];
    const float* pfcW2 = (const float*)d_in[20];
    const float* pfcb2 = (const float*)d_in[21];
    float* out = (float*)d_out;

    static bool attr_set = false;
    if (!attr_set) {
        cudaFuncSetAttribute(gru_scan, cudaFuncAttributeMaxDynamicSharedMemorySize,
                             SCAN_SMEM_BYTES);
        cudaFuncSetAttribute(gemm_proj_mma, cudaFuncAttributeMaxDynamicSharedMemorySize,
                             GEMM_SMEM_BYTES);
        attr_set = true;
    }

    float *pv, *gxs, *gxr, *hwB, *hsB, *hrB;
    cudaGetSymbolAddress((void**)&pv,  g_PV);
    cudaGetSymbolAddress((void**)&gxs, g_GXs);
    cudaGetSymbolAddress((void**)&gxr, g_GXr);
    cudaGetSymbolAddress((void**)&hwB, g_Hw);
    cudaGetSymbolAddress((void**)&hsB, g_Hs);
    cudaGetSymbolAddress((void**)&hrB, g_Hr);

    float* hw1 = hwB + (size_t)2 * NW * HD;
    float* hs1 = hsB + (size_t)2 * NS * HD;
    float* hr1 = hrB + (size_t)2 * NR * HD;

    kinit_bar<<<1, NBAR * BPAD>>>();

    // project full vocabulary once per direction: PV = emb @ Wih^T + bih
    gemm_proj_mma<<<dim3((VOCAB + 127) / 128, G3 / 64, 2), 256, GEMM_SMEM_BYTES>>>(
        emb, nullptr, VOCAB, wWih, wbih, pv);

    // word-level scan (T=32)
    gru_scan<<<dim3(NW / 256, 16, 2), 256, SCAN_SMEM_BYTES>>>(
        hwB, hw1, wWhh, wbhh, nullptr, pv, tok, NW, TW, 0);
    float* hwF = (TW & 1) ? hw1 : hwB;

    // sentence-level: project (hf+hb fused) + scan (T=16)
    gemm_proj_mma<<<dim3((NW + 127) / 128, G3 / 64, 2), 256, GEMM_SMEM_BYTES>>>(
        hwF, hwF + (size_t)NW * HD, NW, sWih, sbih, gxs);
    gru_scan<<<dim3(1, 16, 2), 256, SCAN_SMEM_BYTES>>>(
        hsB, hs1, sWhh, sbhh, gxs, nullptr, nullptr, NS, TS, 16);
    float* hsF = (TS & 1) ? hs1 : hsB;

    // review-star head -> out[8..135]
    fc_head<<<NS, 128>>>(hsF, hsF + (size_t)NS * HD, rfcW1, rfcb1, rfcW2, rfcb2, out + NR);

    // review-level (business) biGRU: project (fused sum) + scan (T=16)
    gemm_proj_mma<<<dim3(1, G3 / 64, 2), 256, GEMM_SMEM_BYTES>>>(
        hsF, hsF + (size_t)NS * HD, NS, rWih, rbih, gxr);
    gru_scan<<<dim3(1, 16, 2), 256, SCAN_SMEM_BYTES>>>(
        hrB, hr1, rWhh, rbhh, gxr, nullptr, nullptr, NR, TR, 18);
    float* hrF = (TR & 1) ? hr1 : hrB;

    // business head -> out[0..7]
    fc_head<<<NR, 128>>>(hrF, hrF + (size_t)NR * HD, pfcW1, pfcb1, pfcW2, pfcb2, out);

    (void)in_sizes; (void)n_in; (void)out_size;
}

// round 10
// speedup vs baseline: 1.0621x; 1.0621x over previous
#include <cuda_runtime.h>
#include <cstdint>

// ---------------- problem constants ----------------
#define HD   256      // hidden / embedding dim
#define G3   768      // 3*H gate dim
#define VOCAB 30000
#define NW   2048     // word-level sequences (B*R*S)
#define TW   32       // word-level timesteps (W)
#define NS   128      // sentence-level sequences (B*R)
#define TS   16       // sentence-level timesteps (S)
#define NR   8        // review-level sequences (B)
#define TR   16       // review-level timesteps (R)

#define SP   36       // smem row stride (mod 32 == 4 -> conflict-free; 16B-aligned)
#define WSP  260      // resident-W row stride (mod 32 == 4; 16B-aligned)

// scan smem: Wres[48*WSP] + Hsm[256*SP]
#define SCAN_SMEM_WORDS (48*WSP + 256*SP)
#define SCAN_SMEM_BYTES (SCAN_SMEM_WORDS * 4)
// gemm smem: double-buffered As[2][128][SP] + Bs[2][64][SP]
#define GEMM_SMEM_WORDS (2*128*SP + 2*64*SP)
#define GEMM_SMEM_BYTES (GEMM_SMEM_WORDS * 4)

#define NBAR 20       // word 0..15, sentence 16..17, review 18..19
#define BPAD 32       // barrier slot padding (128B)

// ---------------- scratch (static device globals; no runtime alloc) ----------------
__device__ float g_PV [(size_t)2*VOCAB*G3];        // projected vocab per dir
__device__ float g_GXs[(size_t)2*NS*TS*G3];        // sentence-level gx
__device__ float g_GXr[(size_t)2*NR*TR*G3];        // review-level gx
__device__ float g_Hw [2][(size_t)2*NW*HD];        // ping-pong hidden, word
__device__ float g_Hs [2][(size_t)2*NS*HD];        // sentence
__device__ float g_Hr [2][(size_t)2*NR*HD];        // review

// grid-barrier state: one padded slot per (scan, dir, rowgroup)
__device__ unsigned g_cnt[NBAR * BPAD];
__device__ volatile unsigned g_phase[NBAR * BPAD];

// ---------------- helpers ----------------
__device__ __forceinline__ float fsigm(float x) {
    float e = __expf(-x);
    return __fdividef(1.f, 1.f + e);
}
__device__ __forceinline__ float ftanh(float x) {
    float ax = fabsf(x);
    float e = __expf(-2.f * ax);
    float r = __fdividef(1.f - e, 1.f + e);
    return copysignf(r, x);
}

__device__ __forceinline__ unsigned f2tf(float x) {
    unsigned u;
    asm("cvt.rna.tf32.f32 %0, %1;" : "=r"(u) : "f"(x));
    return u;
}

__device__ __forceinline__ void mma8(float* d,
                                     unsigned a0, unsigned a1, unsigned a2, unsigned a3,
                                     unsigned b0, unsigned b1) {
    asm volatile(
        "mma.sync.aligned.m16n8k8.row.col.f32.tf32.tf32.f32 "
        "{%0,%1,%2,%3},{%4,%5,%6,%7},{%8,%9},{%0,%1,%2,%3};"
        : "+f"(d[0]), "+f"(d[1]), "+f"(d[2]), "+f"(d[3])
        : "r"(a0), "r"(a1), "r"(a2), "r"(a3), "r"(b0), "r"(b1));
}

__device__ __forceinline__ void ldsm4(unsigned& r0, unsigned& r1, unsigned& r2, unsigned& r3,
                                      unsigned addr) {
    asm volatile("ldmatrix.sync.aligned.m8n8.x4.shared.b16 {%0,%1,%2,%3}, [%4];"
                 : "=r"(r0), "=r"(r1), "=r"(r2), "=r"(r3) : "r"(addr));
}
__device__ __forceinline__ void ldsm2(unsigned& r0, unsigned& r1, unsigned addr) {
    asm volatile("ldmatrix.sync.aligned.m8n8.x2.shared.b16 {%0,%1}, [%2];"
                 : "=r"(r0), "=r"(r1) : "r"(addr));
}

__global__ void kinit_bar() {
    int i = threadIdx.x;
    if (i < NBAR * BPAD) { g_cnt[i] = 0; g_phase[i] = 0; }
}

// software grid barrier over an nCTA-member group (slot = id*BPAD)
__device__ __forceinline__ void gbar(int id, unsigned nCTA, unsigned target) {
    __syncthreads();
    if (threadIdx.x == 0) {
        __threadfence();
        unsigned* cnt = &g_cnt[id * BPAD];
        unsigned old = atomicAdd(cnt, 1u);
        if (old == nCTA - 1u) {
            *cnt = 0u;
            __threadfence();
            g_phase[id * BPAD] = target;
        } else {
            while (g_phase[id * BPAD] < target) __nanosleep(64);
        }
        __threadfence();
    }
    __syncthreads();
}

// ---------------- TF32 GEMM: C[d][M,768] = (A(+A2))[M,256] @ W[d][768,256]^T + bias[d] ----------------
__global__ __launch_bounds__(256, 2)
void gemm_proj_mma(const float* __restrict__ A, const float* __restrict__ A2, int M,
                   const float* __restrict__ W, const float* __restrict__ bias,
                   float* __restrict__ C)
{
    extern __shared__ unsigned gsm[];
    unsigned* As = gsm;                  // [2][128][SP]
    unsigned* Bs = gsm + 2 * 128 * SP;   // [2][64][SP]

    int d = blockIdx.z;
    const float* Wd = W    + (size_t)d * G3 * HD;
    const float* bd = bias + (size_t)d * G3;
    float*       Cd = C    + (size_t)d * M * G3;

    int m0 = blockIdx.x * 128;
    int n0 = blockIdx.y * 64;

    int tid = threadIdx.x, lane = tid & 31, wid = tid >> 5;
    int wm = wid & 3, wn = wid >> 2;
    int RB = wm * 32, CB = wn * 32;
    int g = lane >> 2, c = lane & 3;

    int l7 = lane & 7, ts = lane >> 3;
    int a_row_off = l7 + (ts & 1) * 8;
    int a_col_off = (ts >> 1) * 4;
    unsigned sAs = (unsigned)__cvta_generic_to_shared(As);
    unsigned sBs = (unsigned)__cvta_generic_to_shared(Bs);

    unsigned aAddr[2], bAddr[2];
#pragma unroll
    for (int mt = 0; mt < 2; ++mt)
        aAddr[mt] = sAs + (unsigned)(((RB + mt * 16 + a_row_off) * SP + a_col_off) * 4);
    int ntl = ts >> 1, bcol = (ts & 1) * 4;
#pragma unroll
    for (int p = 0; p < 2; ++p)
        bAddr[p] = sBs + (unsigned)(((CB + (2 * p + ntl) * 8 + l7) * SP + bcol) * 4);

    float acc[2][4][4];
#pragma unroll
    for (int i = 0; i < 2; ++i)
#pragma unroll
        for (int j = 0; j < 4; ++j)
#pragma unroll
            for (int k = 0; k < 4; ++k) acc[i][j][k] = 0.f;

    int lr = tid >> 3, lq = tid & 7;

    float4 pa[4], pw[2];
#pragma unroll
    for (int it = 0; it < 4; ++it) {
        int r = lr + it * 32;
        pa[it] = make_float4(0.f, 0.f, 0.f, 0.f);
        if (m0 + r < M) {
            size_t off = (size_t)(m0 + r) * HD + lq * 4;
            pa[it] = *(const float4*)(A + off);
            if (A2) {
                float4 b = *(const float4*)(A2 + off);
                pa[it].x += b.x; pa[it].y += b.y; pa[it].z += b.z; pa[it].w += b.w;
            }
        }
    }
#pragma unroll
    for (int it = 0; it < 2; ++it) {
        int r = lr + it * 32;
        pw[it] = *(const float4*)(Wd + (size_t)(n0 + r) * HD + lq * 4);
    }
#pragma unroll
    for (int it = 0; it < 4; ++it) {
        int r = lr + it * 32;
        *(uint4*)(As + (size_t)r * SP + lq * 4) =
            make_uint4(f2tf(pa[it].x), f2tf(pa[it].y), f2tf(pa[it].z), f2tf(pa[it].w));
    }
#pragma unroll
    for (int it = 0; it < 2; ++it) {
        int r = lr + it * 32;
        *(uint4*)(Bs + (size_t)r * SP + lq * 4) =
            make_uint4(f2tf(pw[it].x), f2tf(pw[it].y), f2tf(pw[it].z), f2tf(pw[it].w));
    }
    __syncthreads();

    for (int k0i = 0; k0i < 8; ++k0i) {
        int cur = k0i & 1;
        if (k0i < 7) {
            int k0 = (k0i + 1) * 32;
#pragma unroll
            for (int it = 0; it < 4; ++it) {
                int r = lr + it * 32;
                pa[it] = make_float4(0.f, 0.f, 0.f, 0.f);
                if (m0 + r < M) {
                    size_t off = (size_t)(m0 + r) * HD + k0 + lq * 4;
                    pa[it] = *(const float4*)(A + off);
                    if (A2) {
                        float4 b = *(const float4*)(A2 + off);
                        pa[it].x += b.x; pa[it].y += b.y; pa[it].z += b.z; pa[it].w += b.w;
                    }
                }
            }
#pragma unroll
            for (int it = 0; it < 2; ++it) {
                int r = lr + it * 32;
                pw[it] = *(const float4*)(Wd + (size_t)(n0 + r) * HD + k0 + lq * 4);
            }
        }

        unsigned aBuf = (unsigned)(cur * 128 * SP * 4);
        unsigned bBuf = (unsigned)(cur * 64 * SP * 4);
#pragma unroll
        for (int ks = 0; ks < 4; ++ks) {
            unsigned kbo = (unsigned)(ks * 32);
            unsigned a[2][4];
#pragma unroll
            for (int mt = 0; mt < 2; ++mt)
                ldsm4(a[mt][0], a[mt][1], a[mt][2], a[mt][3], aAddr[mt] + aBuf + kbo);
            unsigned b[4][2];
#pragma unroll
            for (int p = 0; p < 2; ++p)
                ldsm4(b[2*p][0], b[2*p][1], b[2*p+1][0], b[2*p+1][1], bAddr[p] + bBuf + kbo);
#pragma unroll
            for (int nt = 0; nt < 4; ++nt)
#pragma unroll
                for (int mt = 0; mt < 2; ++mt)
                    mma8(acc[mt][nt], a[mt][0], a[mt][1], a[mt][2], a[mt][3],
                         b[nt][0], b[nt][1]);
        }

        if (k0i < 7) {
            unsigned* An = As + (size_t)(cur ^ 1) * 128 * SP;
            unsigned* Bn = Bs + (size_t)(cur ^ 1) * 64 * SP;
#pragma unroll
            for (int it = 0; it < 4; ++it) {
                int r = lr + it * 32;
                *(uint4*)(An + (size_t)r * SP + lq * 4) =
                    make_uint4(f2tf(pa[it].x), f2tf(pa[it].y), f2tf(pa[it].z), f2tf(pa[it].w));
            }
#pragma unroll
            for (int it = 0; it < 2; ++it) {
                int r = lr + it * 32;
                *(uint4*)(Bn + (size_t)r * SP + lq * 4) =
                    make_uint4(f2tf(pw[it].x), f2tf(pw[it].y), f2tf(pw[it].z), f2tf(pw[it].w));
            }
        }
        __syncthreads();
    }

#pragma unroll
    for (int nt = 0; nt < 4; ++nt) {
        int col = n0 + CB + nt * 8 + 2 * c;
        float2 bb = *(const float2*)(bd + col);
#pragma unroll
        for (int mt = 0; mt < 2; ++mt) {
            int row0 = m0 + RB + mt * 16 + g;
            if (row0 < M) {
                float2 o = make_float2(acc[mt][nt][0] + bb.x, acc[mt][nt][1] + bb.y);
                *(float2*)(Cd + (size_t)row0 * G3 + col) = o;
            }
            int row1 = row0 + 8;
            if (row1 < M) {
                float2 o = make_float2(acc[mt][nt][2] + bb.x, acc[mt][nt][3] + bb.y);
                *(float2*)(Cd + (size_t)row1 * G3 + col) = o;
            }
        }
    }
}

// ---------------- persistent fused GRU scan (Round-8 inner loop) ----------------
// CTA: 256 rows x 16 j-cols x 3 gates; W resident in smem; 2 CTAs/SM.
// H staged via registers (uint4 LDG, raw tf32 bits); 32-k chunks, 8 syncs/step.
// Per-(dir, rowgroup) barrier (16 CTAs); skipped after the final step.
__global__ __launch_bounds__(256, 2)
void gru_scan(float* __restrict__ H0, float* __restrict__ H1,
              const float* __restrict__ Whh,   // [2][768][256]
              const float* __restrict__ bhh,   // [2][768]
              const float* __restrict__ GX,    // [2][N*T][768] or nullptr
              const float* __restrict__ PV,    // [2][VOCAB][768] or nullptr
              const int*   __restrict__ tok,   // tokens or nullptr
              int N, int T, int barBase)
{
    extern __shared__ unsigned smem[];
    unsigned* Wres = smem;                                     // [48][WSP]
    unsigned (*Hsm)[SP] = (unsigned(*)[SP])(smem + 48 * WSP);  // [256][SP]

    int d  = blockIdx.z;
    int n0 = blockIdx.x * 256;
    int j0 = blockIdx.y * 16;
    int bid = barBase + d * gridDim.x + blockIdx.x;

    const float* Wd = Whh + (size_t)d * G3 * HD;

    int tid = threadIdx.x, lane = tid & 31, wid = tid >> 5;
    int wm = wid & 3, wn = wid >> 2;
    int RB = wm * 64, CB = wn * 8;
    int g = lane >> 2, c = lane & 3;

    // ---- load resident W slice (RNA-converted once) ----
    for (int idx = tid; idx < 48 * 64; idx += 256) {
        int row = idx >> 6;
        int c4  = idx & 63;
        int gt = row >> 4, j = row & 15;
        float4 v = *(const float4*)(Wd + (size_t)(gt * 256 + j0 + j) * HD + c4 * 4);
        *(uint4*)(Wres + (size_t)row * WSP + c4 * 4) =
            make_uint4(f2tf(v.x), f2tf(v.y), f2tf(v.z), f2tf(v.w));
    }
    __syncthreads();

    int l7 = lane & 7, ts = lane >> 3;
    int a_row_off = l7 + (ts & 1) * 8;
    int a_col_off = (ts >> 1) * 4;
    unsigned sH = (unsigned)__cvta_generic_to_shared(Hsm);
    unsigned sW = (unsigned)__cvta_generic_to_shared(Wres);

    unsigned aAddr[4];
#pragma unroll
    for (int mt = 0; mt < 4; ++mt)
        aAddr[mt] = sH + (unsigned)(((RB + mt * 16 + a_row_off) * SP + a_col_off) * 4);
    unsigned bAddr01 = sW + (unsigned)((((ts >> 1) * 16 + CB + l7) * WSP + (ts & 1) * 4) * 4);
    unsigned bAddr2  = sW + (unsigned)(((32 + CB + l7) * WSP + ((ts & 1) * 4)) * 4);

    bool is64 = false;
    if (tok) is64 = (tok[1] == 0) & (tok[3] == 0) & (tok[5] == 0) & (tok[7] == 0);

    int cc = j0 + CB + 2 * c;
    float2 br2 = *(const float2*)(bhh + (size_t)d * G3 + cc);
    float2 bz2 = *(const float2*)(bhh + (size_t)d * G3 + 256 + cc);
    float2 bn2 = *(const float2*)(bhh + (size_t)d * G3 + 512 + cc);

    int lr = tid >> 3, lq = tid & 7;

    // this thread's 8 row instances
    int rowi[8];
#pragma unroll
    for (int idx = 0; idx < 8; ++idx) {
        int mt = idx >> 1, half = idx & 1;
        rowi[idx] = n0 + RB + mt * 16 + g + half * 8;
    }

    for (int t = 0; t < T; ++t) {
        const float* Hin  = (t & 1) ? H1 : H0;
        float*       Hout = (t & 1) ? H0 : H1;
        int teff = d ? (T - 1 - t) : t;

        // gx row pointers for this step (loaded in the epilogue)
        const float* gxp[8];
#pragma unroll
        for (int idx = 0; idx < 8; ++idx) {
            int r = rowi[idx];
            if (r < N) {
                if (tok) {
                    int ti = r * T + teff;
                    int tv = is64 ? tok[2 * (size_t)ti] : tok[ti];
                    gxp[idx] = PV + ((size_t)d * VOCAB + tv) * G3;
                } else {
                    gxp[idx] = GX + ((size_t)d * N * T + (size_t)r * T + teff) * G3;
                }
            } else gxp[idx] = PV ? PV : GX;
        }

        float acc[3][4][4];
#pragma unroll
        for (int i = 0; i < 3; ++i)
#pragma unroll
            for (int j = 0; j < 4; ++j)
#pragma unroll
                for (int k = 0; k < 4; ++k) acc[i][j][k] = 0.f;

        if (t > 0) {   // step 0: Hin == 0 -> Gh == 0, skip entirely
            uint4 ph[8];
#pragma unroll
            for (int it = 0; it < 8; ++it) {
                int r = lr + it * 32;
                ph[it] = make_uint4(0u, 0u, 0u, 0u);
                if (n0 + r < N)
                    ph[it] = *(const uint4*)(Hin + (size_t)(d * N + n0 + r) * HD + lq * 4);
            }

            for (int k0i = 0; k0i < 8; ++k0i) {
#pragma unroll
                for (int it = 0; it < 8; ++it) {
                    int r = lr + it * 32;
                    *(uint4*)(&Hsm[r][lq * 4]) = ph[it];   // raw fp32 bits -> tf32 trunc
                }
                __syncthreads();

                if (k0i < 7) {
                    int k0 = (k0i + 1) * 32;
#pragma unroll
                    for (int it = 0; it < 8; ++it) {
                        int r = lr + it * 32;
                        ph[it] = make_uint4(0u, 0u, 0u, 0u);
                        if (n0 + r < N)
                            ph[it] = *(const uint4*)(Hin + (size_t)(d * N + n0 + r) * HD + k0 + lq * 4);
                    }
                }

                unsigned kwo = (unsigned)(k0i * 128);
#pragma unroll
                for (int ks = 0; ks < 4; ++ks) {
                    unsigned kbo = (unsigned)(ks * 32);
                    unsigned a[4][4];
#pragma unroll
                    for (int mt = 0; mt < 4; ++mt)
                        ldsm4(a[mt][0], a[mt][1], a[mt][2], a[mt][3], aAddr[mt] + kbo);
                    unsigned b00, b01, b10, b11, b20, b21;
                    ldsm4(b00, b01, b10, b11, bAddr01 + kwo + kbo);
                    ldsm2(b20, b21, bAddr2 + kwo + kbo);
#pragma unroll
                    for (int mt = 0; mt < 4; ++mt) {
                        mma8(acc[0][mt], a[mt][0], a[mt][1], a[mt][2], a[mt][3], b00, b01);
                        mma8(acc[1][mt], a[mt][0], a[mt][1], a[mt][2], a[mt][3], b10, b11);
                        mma8(acc[2][mt], a[mt][0], a[mt][1], a[mt][2], a[mt][3], b20, b21);
                    }
                }
                __syncthreads();
            }
        }

        // ---- gate math epilogue: 8 instances in 2 phases of 4 ----
#pragma unroll
        for (int phx = 0; phx < 2; ++phx) {
            float2 GR[4], GZ[4], GN[4], HH[4];
            bool val[4];
#pragma unroll
            for (int i = 0; i < 4; ++i) {
                int idx = phx * 4 + i;
                int r = rowi[idx];
                val[i] = (r < N);
                GR[i] = GZ[i] = GN[i] = HH[i] = make_float2(0.f, 0.f);
                if (val[i]) {
                    const float* gxrow = gxp[idx];
                    GR[i] = *(const float2*)(gxrow + cc);
                    GZ[i] = *(const float2*)(gxrow + 256 + cc);
                    GN[i] = *(const float2*)(gxrow + 512 + cc);
                    if (t > 0) HH[i] = *(const float2*)(Hin + (size_t)(d * N + r) * HD + cc);
                }
            }
#pragma unroll
            for (int i = 0; i < 4; ++i) {
                if (!val[i]) continue;
                int idx = phx * 4 + i;
                int mt = idx >> 1, half = idx & 1;
                float aR0 = acc[0][mt][half * 2 + 0], aR1 = acc[0][mt][half * 2 + 1];
                float aZ0 = acc[1][mt][half * 2 + 0], aZ1 = acc[1][mt][half * 2 + 1];
                float aN0 = acc[2][mt][half * 2 + 0], aN1 = acc[2][mt][half * 2 + 1];

                float r0 = fsigm(GR[i].x + aR0 + br2.x);
                float r1 = fsigm(GR[i].y + aR1 + br2.y);
                float z0 = fsigm(GZ[i].x + aZ0 + bz2.x);
                float z1 = fsigm(GZ[i].y + aZ1 + bz2.y);
                float n0v = ftanh(GN[i].x + r0 * (aN0 + bn2.x));
                float n1v = ftanh(GN[i].y + r1 * (aN1 + bn2.y));

                float2 o;
                o.x = n0v + z0 * (HH[i].x - n0v);
                o.y = n1v + z1 * (HH[i].y - n1v);
                *(float2*)(Hout + (size_t)(d * N + rowi[idx]) * HD + cc) = o;
            }
        }

        if (t + 1 < T) gbar(bid, 16, (unsigned)(t + 1));
    }
}

// ---------------- FC head: Linear(256->128) -> SELU -> Linear(128->1) on (X+X2) ----------------
__global__ void fc_head(const float* __restrict__ X, const float* __restrict__ X2,
                        const float* __restrict__ W1, const float* __restrict__ b1,
                        const float* __restrict__ W2, const float* __restrict__ b2,
                        float* __restrict__ out)
{
    int row = blockIdx.x;
    int h = threadIdx.x;  // 128 threads
    const float* x  = X  + (size_t)row * HD;
    const float* x2 = X2 + (size_t)row * HD;
    const float* w  = W1 + (size_t)h * HD;
    float s = 0.f;
#pragma unroll 8
    for (int k = 0; k < HD; k += 4) {
        float4 xv = *(const float4*)(x + k);
        float4 yv = *(const float4*)(x2 + k);
        float4 wv = *(const float4*)(w + k);
        s += (xv.x + yv.x) * wv.x + (xv.y + yv.y) * wv.y
           + (xv.z + yv.z) * wv.z + (xv.w + yv.w) * wv.w;
    }
    s += b1[h];
    const float SC = 1.0507009873554805f, AL = 1.6732632423543772f;
    float selu = SC * (s > 0.f ? s : AL * expm1f(s));
    float v = selu * W2[h];
    __shared__ float red[128];
    red[h] = v; __syncthreads();
    for (int st = 64; st > 0; st >>= 1) {
        if (h < st) red[h] += red[h + st];
        __syncthreads();
    }
    if (h == 0) out[row] = red[0] + b2[0];
}

// ---------------- launch ----------------
extern "C" void kernel_launch(void* const* d_in, const int* in_sizes, int n_in,
                              void* d_out, int out_size)
{
    const int*   tok   = (const int*)  d_in[0];
    const float* emb   = (const float*)d_in[1];
    const float* wWih  = (const float*)d_in[2];
    const float* wWhh  = (const float*)d_in[3];
    const float* wbih  = (const float*)d_in[4];
    const float* wbhh  = (const float*)d_in[5];
    const float* sWih  = (const float*)d_in[6];
    const float* sWhh  = (const float*)d_in[7];
    const float* sbih  = (const float*)d_in[8];
    const float* sbhh  = (const float*)d_in[9];
    const float* rWih  = (const float*)d_in[10];
    const float* rWhh  = (const float*)d_in[11];
    const float* rbih  = (const float*)d_in[12];
    const float* rbhh  = (const float*)d_in[13];
    const float* rfcW1 = (const float*)d_in[14];
    const float* rfcb1 = (const float*)d_in[15];
    const float* rfcW2 = (const float*)d_in[16];
    const float* rfcb2 = (const float*)d_in[17];
    const float* pfcW1 = (const float*)d_in[18];
    const float* pfcb1 = (const float*)d_in[19];
    const float* pfcW2 = (const float*)d_in[20];
    const float* pfcb2 = (const float*)d_in[21];
    float* out = (float*)d_out;

    static bool attr_set = false;
    if (!attr_set) {
        cudaFuncSetAttribute(gru_scan, cudaFuncAttributeMaxDynamicSharedMemorySize,
                             SCAN_SMEM_BYTES);
        cudaFuncSetAttribute(gemm_proj_mma, cudaFuncAttributeMaxDynamicSharedMemorySize,
                             GEMM_SMEM_BYTES);
        attr_set = true;
    }

    float *pv, *gxs, *gxr, *hwB, *hsB, *hrB;
    cudaGetSymbolAddress((void**)&pv,  g_PV);
    cudaGetSymbolAddress((void**)&gxs, g_GXs);
    cudaGetSymbolAddress((void**)&gxr, g_GXr);
    cudaGetSymbolAddress((void**)&hwB, g_Hw);
    cudaGetSymbolAddress((void**)&hsB, g_Hs);
    cudaGetSymbolAddress((void**)&hrB, g_Hr);

    float* hw1 = hwB + (size_t)2 * NW * HD;
    float* hs1 = hsB + (size_t)2 * NS * HD;
    float* hr1 = hrB + (size_t)2 * NR * HD;

    kinit_bar<<<1, NBAR * BPAD>>>();

    // project full vocabulary once per direction: PV = emb @ Wih^T + bih
    gemm_proj_mma<<<dim3((VOCAB + 127) / 128, G3 / 64, 2), 256, GEMM_SMEM_BYTES>>>(
        emb, nullptr, VOCAB, wWih, wbih, pv);

    // word-level scan (T=32)
    gru_scan<<<dim3(NW / 256, 16, 2), 256, SCAN_SMEM_BYTES>>>(
        hwB, hw1, wWhh, wbhh, nullptr, pv, tok, NW, TW, 0);
    float* hwF = (TW & 1) ? hw1 : hwB;

    // sentence-level: project (hf+hb fused) + scan (T=16)
    gemm_proj_mma<<<dim3((NW + 127) / 128, G3 / 64, 2), 256, GEMM_SMEM_BYTES>>>(
        hwF, hwF + (size_t)NW * HD, NW, sWih, sbih, gxs);
    gru_scan<<<dim3(1, 16, 2), 256, SCAN_SMEM_BYTES>>>(
        hsB, hs1, sWhh, sbhh, gxs, nullptr, nullptr, NS, TS, 16);
    float* hsF = (TS & 1) ? hs1 : hsB;

    // review-star head -> out[8..135]
    fc_head<<<NS, 128>>>(hsF, hsF + (size_t)NS * HD, rfcW1, rfcb1, rfcW2, rfcb2, out + NR);

    // review-level (business) biGRU: project (fused sum) + scan (T=16)
    gemm_proj_mma<<<dim3(1, G3 / 64, 2), 256, GEMM_SMEM_BYTES>>>(
        hsF, hsF + (size_t)NS * HD, NS, rWih, rbih, gxr);
    gru_scan<<<dim3(1, 16, 2), 256, SCAN_SMEM_BYTES>>>(
        hrB, hr1, rWhh, rbhh, gxr, nullptr, nullptr, NR, TR, 18);
    float* hrF = (TR & 1) ? hr1 : hrB;

    // business head -> out[0..7]
    fc_head<<<NR, 128>>>(hrF, hrF + (size_t)NR * HD, pfcW1, pfcb1, pfcW2, pfcb2, out);

    (void)in_sizes; (void)n_in; (void)out_size;
}

// round 11
// speedup vs baseline: 1.1167x; 1.0514x over previous
#include <cuda_runtime.h>
#include <cstdint>

// ---------------- problem constants ----------------
#define HD   256      // hidden / embedding dim
#define G3   768      // 3*H gate dim
#define VOCAB 30000
#define NW   2048     // word-level sequences (B*R*S)
#define TW   32       // word-level timesteps (W)
#define NS   128      // sentence-level sequences (B*R)
#define TS   16       // sentence-level timesteps (S)
#define NR   8        // review-level sequences (B)
#define TR   16       // review-level timesteps (R)

#define SP   36       // smem row stride (mod 32 == 4 -> conflict-free; 16B-aligned)
#define WSP  260      // resident-W row stride (mod 32 == 4; 16B-aligned)

// scan smem: Wres[48*WSP] + Hsm[256*SP]
#define SCAN_SMEM_WORDS (48*WSP + 256*SP)
#define SCAN_SMEM_BYTES (SCAN_SMEM_WORDS * 4)
// gemm smem: double-buffered As[2][128][SP] + Bs[2][64][SP]
#define GEMM_SMEM_WORDS (2*128*SP + 2*64*SP)
#define GEMM_SMEM_BYTES (GEMM_SMEM_WORDS * 4)

#define NBAR 20       // word 0..15, sentence 16..17, review 18..19
#define BPAD 32       // barrier slot padding (128B)

// ---------------- scratch (static device globals; no runtime alloc) ----------------
__device__ float g_PV [(size_t)2*VOCAB*G3];        // projected vocab per dir
__device__ float g_GXs[(size_t)2*NS*TS*G3];        // sentence-level gx
__device__ float g_GXr[(size_t)2*NR*TR*G3];        // review-level gx
__device__ float g_Hw [2][(size_t)2*NW*HD];        // ping-pong hidden, word
__device__ float g_Hs [2][(size_t)2*NS*HD];        // sentence
__device__ float g_Hr [2][(size_t)2*NR*HD];        // review

// grid-barrier state: one padded slot per (scan, dir, rowgroup)
__device__ unsigned g_cnt[NBAR * BPAD];
__device__ volatile unsigned g_phase[NBAR * BPAD];

// ---------------- helpers ----------------
__device__ __forceinline__ float fsigm(float x) {
    float e = __expf(-x);
    return __fdividef(1.f, 1.f + e);
}
__device__ __forceinline__ float ftanh(float x) {
    float ax = fabsf(x);
    float e = __expf(-2.f * ax);
    float r = __fdividef(1.f - e, 1.f + e);
    return copysignf(r, x);
}

__device__ __forceinline__ unsigned f2tf(float x) {
    unsigned u;
    asm("cvt.rna.tf32.f32 %0, %1;" : "=r"(u) : "f"(x));
    return u;
}

__device__ __forceinline__ void mma8(float* d,
                                     unsigned a0, unsigned a1, unsigned a2, unsigned a3,
                                     unsigned b0, unsigned b1) {
    asm volatile(
        "mma.sync.aligned.m16n8k8.row.col.f32.tf32.tf32.f32 "
        "{%0,%1,%2,%3},{%4,%5,%6,%7},{%8,%9},{%0,%1,%2,%3};"
        : "+f"(d[0]), "+f"(d[1]), "+f"(d[2]), "+f"(d[3])
        : "r"(a0), "r"(a1), "r"(a2), "r"(a3), "r"(b0), "r"(b1));
}

__device__ __forceinline__ void ldsm4(unsigned& r0, unsigned& r1, unsigned& r2, unsigned& r3,
                                      unsigned addr) {
    asm volatile("ldmatrix.sync.aligned.m8n8.x4.shared.b16 {%0,%1,%2,%3}, [%4];"
                 : "=r"(r0), "=r"(r1), "=r"(r2), "=r"(r3) : "r"(addr));
}
__device__ __forceinline__ void ldsm2(unsigned& r0, unsigned& r1, unsigned addr) {
    asm volatile("ldmatrix.sync.aligned.m8n8.x2.shared.b16 {%0,%1}, [%2];"
                 : "=r"(r0), "=r"(r1) : "r"(addr));
}

// 2-warp named barrier (64 threads), ids 1..4
__device__ __forceinline__ void barpair(int id) {
    asm volatile("bar.sync %0, 64;" :: "r"(id) : "memory");
}

__global__ void kinit_bar() {
    int i = threadIdx.x;
    if (i < NBAR * BPAD) { g_cnt[i] = 0; g_phase[i] = 0; }
}

// software grid barrier over an nCTA-member group (slot = id*BPAD)
__device__ __forceinline__ void gbar(int id, unsigned nCTA, unsigned target) {
    __syncthreads();
    if (threadIdx.x == 0) {
        __threadfence();
        unsigned* cnt = &g_cnt[id * BPAD];
        unsigned old = atomicAdd(cnt, 1u);
        if (old == nCTA - 1u) {
            *cnt = 0u;
            __threadfence();
            g_phase[id * BPAD] = target;
        } else {
            while (g_phase[id * BPAD] < target) __nanosleep(32);
        }
        __threadfence();
    }
    __syncthreads();
}

// ---------------- TF32 GEMM: C[d][M,768] = (A(+A2))[M,256] @ W[d][768,256]^T + bias[d] ----------------
__global__ __launch_bounds__(256, 2)
void gemm_proj_mma(const float* __restrict__ A, const float* __restrict__ A2, int M,
                   const float* __restrict__ W, const float* __restrict__ bias,
                   float* __restrict__ C)
{
    extern __shared__ unsigned gsm[];
    unsigned* As = gsm;                  // [2][128][SP]
    unsigned* Bs = gsm + 2 * 128 * SP;   // [2][64][SP]

    int d = blockIdx.z;
    const float* Wd = W    + (size_t)d * G3 * HD;
    const float* bd = bias + (size_t)d * G3;
    float*       Cd = C    + (size_t)d * M * G3;

    int m0 = blockIdx.x * 128;
    int n0 = blockIdx.y * 64;

    int tid = threadIdx.x, lane = tid & 31, wid = tid >> 5;
    int wm = wid & 3, wn = wid >> 2;
    int RB = wm * 32, CB = wn * 32;
    int g = lane >> 2, c = lane & 3;

    int l7 = lane & 7, ts = lane >> 3;
    int a_row_off = l7 + (ts & 1) * 8;
    int a_col_off = (ts >> 1) * 4;
    unsigned sAs = (unsigned)__cvta_generic_to_shared(As);
    unsigned sBs = (unsigned)__cvta_generic_to_shared(Bs);

    unsigned aAddr[2], bAddr[2];
#pragma unroll
    for (int mt = 0; mt < 2; ++mt)
        aAddr[mt] = sAs + (unsigned)(((RB + mt * 16 + a_row_off) * SP + a_col_off) * 4);
    int ntl = ts >> 1, bcol = (ts & 1) * 4;
#pragma unroll
    for (int p = 0; p < 2; ++p)
        bAddr[p] = sBs + (unsigned)(((CB + (2 * p + ntl) * 8 + l7) * SP + bcol) * 4);

    float acc[2][4][4];
#pragma unroll
    for (int i = 0; i < 2; ++i)
#pragma unroll
        for (int j = 0; j < 4; ++j)
#pragma unroll
            for (int k = 0; k < 4; ++k) acc[i][j][k] = 0.f;

    int lr = tid >> 3, lq = tid & 7;

    float4 pa[4], pw[2];
#pragma unroll
    for (int it = 0; it < 4; ++it) {
        int r = lr + it * 32;
        pa[it] = make_float4(0.f, 0.f, 0.f, 0.f);
        if (m0 + r < M) {
            size_t off = (size_t)(m0 + r) * HD + lq * 4;
            pa[it] = *(const float4*)(A + off);
            if (A2) {
                float4 b = *(const float4*)(A2 + off);
                pa[it].x += b.x; pa[it].y += b.y; pa[it].z += b.z; pa[it].w += b.w;
            }
        }
    }
#pragma unroll
    for (int it = 0; it < 2; ++it) {
        int r = lr + it * 32;
        pw[it] = *(const float4*)(Wd + (size_t)(n0 + r) * HD + lq * 4);
    }
#pragma unroll
    for (int it = 0; it < 4; ++it) {
        int r = lr + it * 32;
        *(uint4*)(As + (size_t)r * SP + lq * 4) =
            make_uint4(f2tf(pa[it].x), f2tf(pa[it].y), f2tf(pa[it].z), f2tf(pa[it].w));
    }
#pragma unroll
    for (int it = 0; it < 2; ++it) {
        int r = lr + it * 32;
        *(uint4*)(Bs + (size_t)r * SP + lq * 4) =
            make_uint4(f2tf(pw[it].x), f2tf(pw[it].y), f2tf(pw[it].z), f2tf(pw[it].w));
    }
    __syncthreads();

    for (int k0i = 0; k0i < 8; ++k0i) {
        int cur = k0i & 1;
        if (k0i < 7) {
            int k0 = (k0i + 1) * 32;
#pragma unroll
            for (int it = 0; it < 4; ++it) {
                int r = lr + it * 32;
                pa[it] = make_float4(0.f, 0.f, 0.f, 0.f);
                if (m0 + r < M) {
                    size_t off = (size_t)(m0 + r) * HD + k0 + lq * 4;
                    pa[it] = *(const float4*)(A + off);
                    if (A2) {
                        float4 b = *(const float4*)(A2 + off);
                        pa[it].x += b.x; pa[it].y += b.y; pa[it].z += b.z; pa[it].w += b.w;
                    }
                }
            }
#pragma unroll
            for (int it = 0; it < 2; ++it) {
                int r = lr + it * 32;
                pw[it] = *(const float4*)(Wd + (size_t)(n0 + r) * HD + k0 + lq * 4);
            }
        }

        unsigned aBuf = (unsigned)(cur * 128 * SP * 4);
        unsigned bBuf = (unsigned)(cur * 64 * SP * 4);
#pragma unroll
        for (int ks = 0; ks < 4; ++ks) {
            unsigned kbo = (unsigned)(ks * 32);
            unsigned a[2][4];
#pragma unroll
            for (int mt = 0; mt < 2; ++mt)
                ldsm4(a[mt][0], a[mt][1], a[mt][2], a[mt][3], aAddr[mt] + aBuf + kbo);
            unsigned b[4][2];
#pragma unroll
            for (int p = 0; p < 2; ++p)
                ldsm4(b[2*p][0], b[2*p][1], b[2*p+1][0], b[2*p+1][1], bAddr[p] + bBuf + kbo);
#pragma unroll
            for (int nt = 0; nt < 4; ++nt)
#pragma unroll
                for (int mt = 0; mt < 2; ++mt)
                    mma8(acc[mt][nt], a[mt][0], a[mt][1], a[mt][2], a[mt][3],
                         b[nt][0], b[nt][1]);
        }

        if (k0i < 7) {
            unsigned* An = As + (size_t)(cur ^ 1) * 128 * SP;
            unsigned* Bn = Bs + (size_t)(cur ^ 1) * 64 * SP;
#pragma unroll
            for (int it = 0; it < 4; ++it) {
                int r = lr + it * 32;
                *(uint4*)(An + (size_t)r * SP + lq * 4) =
                    make_uint4(f2tf(pa[it].x), f2tf(pa[it].y), f2tf(pa[it].z), f2tf(pa[it].w));
            }
#pragma unroll
            for (int it = 0; it < 2; ++it) {
                int r = lr + it * 32;
                *(uint4*)(Bn + (size_t)r * SP + lq * 4) =
                    make_uint4(f2tf(pw[it].x), f2tf(pw[it].y), f2tf(pw[it].z), f2tf(pw[it].w));
            }
        }
        __syncthreads();
    }

#pragma unroll
    for (int nt = 0; nt < 4; ++nt) {
        int col = n0 + CB + nt * 8 + 2 * c;
        float2 bb = *(const float2*)(bd + col);
#pragma unroll
        for (int mt = 0; mt < 2; ++mt) {
            int row0 = m0 + RB + mt * 16 + g;
            if (row0 < M) {
                float2 o = make_float2(acc[mt][nt][0] + bb.x, acc[mt][nt][1] + bb.y);
                *(float2*)(Cd + (size_t)row0 * G3 + col) = o;
            }
            int row1 = row0 + 8;
            if (row1 < M) {
                float2 o = make_float2(acc[mt][nt][2] + bb.x, acc[mt][nt][3] + bb.y);
                *(float2*)(Cd + (size_t)row1 * G3 + col) = o;
            }
        }
    }
}

// ---------------- persistent fused GRU scan ----------------
// CTA: 256 rows x 16 j-cols x 3 gates; W resident in smem; 2 CTAs/SM.
// H staged slab-locally: warp pair (wm, wm+4) owns rows [wm*64, wm*64+64);
// per-chunk sync is a 2-warp named barrier (no block-wide coupling).
// Per-(dir, rowgroup) grid barrier (16 CTAs); skipped after the final step.
__global__ __launch_bounds__(256, 2)
void gru_scan(float* __restrict__ H0, float* __restrict__ H1,
              const float* __restrict__ Whh,   // [2][768][256]
              const float* __restrict__ bhh,   // [2][768]
              const float* __restrict__ GX,    // [2][N*T][768] or nullptr
              const float* __restrict__ PV,    // [2][VOCAB][768] or nullptr
              const int*   __restrict__ tok,   // tokens or nullptr
              int N, int T, int barBase)
{
    extern __shared__ unsigned smem[];
    unsigned* Wres = smem;                                     // [48][WSP]
    unsigned (*Hsm)[SP] = (unsigned(*)[SP])(smem + 48 * WSP);  // [256][SP]

    int d  = blockIdx.z;
    int n0 = blockIdx.x * 256;
    int j0 = blockIdx.y * 16;
    int bid = barBase + d * gridDim.x + blockIdx.x;

    const float* Wd = Whh + (size_t)d * G3 * HD;

    int tid = threadIdx.x, lane = tid & 31, wid = tid >> 5;
    int wm = wid & 3, wn = wid >> 2;
    int RB = wm * 64, CB = wn * 8;
    int g = lane >> 2, c = lane & 3;

    // ---- load resident W slice (RNA-converted once) ----
    for (int idx = tid; idx < 48 * 64; idx += 256) {
        int row = idx >> 6;
        int c4  = idx & 63;
        int gt = row >> 4, j = row & 15;
        float4 v = *(const float4*)(Wd + (size_t)(gt * 256 + j0 + j) * HD + c4 * 4);
        *(uint4*)(Wres + (size_t)row * WSP + c4 * 4) =
            make_uint4(f2tf(v.x), f2tf(v.y), f2tf(v.z), f2tf(v.w));
    }
    __syncthreads();

    int l7 = lane & 7, ts = lane >> 3;
    int a_row_off = l7 + (ts & 1) * 8;
    int a_col_off = (ts >> 1) * 4;
    unsigned sH = (unsigned)__cvta_generic_to_shared(Hsm);
    unsigned sW = (unsigned)__cvta_generic_to_shared(Wres);

    unsigned aAddr[4];
#pragma unroll
    for (int mt = 0; mt < 4; ++mt)
        aAddr[mt] = sH + (unsigned)(((RB + mt * 16 + a_row_off) * SP + a_col_off) * 4);
    unsigned bAddr01 = sW + (unsigned)((((ts >> 1) * 16 + CB + l7) * WSP + (ts & 1) * 4) * 4);
    unsigned bAddr2  = sW + (unsigned)(((32 + CB + l7) * WSP + ((ts & 1) * 4)) * 4);

    bool is64 = false;
    if (tok) is64 = (tok[1] == 0) & (tok[3] == 0) & (tok[5] == 0) & (tok[7] == 0);

    int cc = j0 + CB + 2 * c;
    float2 br2 = *(const float2*)(bhh + (size_t)d * G3 + cc);
    float2 bz2 = *(const float2*)(bhh + (size_t)d * G3 + 256 + cc);
    float2 bn2 = *(const float2*)(bhh + (size_t)d * G3 + 512 + cc);

    // slab-local staging indices: this warp writes rows [stageBase, +32), 4 rows/it
    int stageBase = wm * 64 + wn * 32;
    int srow = stageBase + (lane >> 3);     // + it*4
    int sq   = lane & 7;
    int barId = wm + 1;                      // named barrier ids 1..4

    // this thread's 8 epilogue row instances
    int rowi[8];
#pragma unroll
    for (int idx = 0; idx < 8; ++idx) {
        int mt = idx >> 1, half = idx & 1;
        rowi[idx] = n0 + RB + mt * 16 + g + half * 8;
    }

    for (int t = 0; t < T; ++t) {
        const float* Hin  = (t & 1) ? H1 : H0;
        float*       Hout = (t & 1) ? H0 : H1;
        int teff = d ? (T - 1 - t) : t;

        // gx row pointers for this step (loaded in the epilogue)
        const float* gxp[8];
#pragma unroll
        for (int idx = 0; idx < 8; ++idx) {
            int r = rowi[idx];
            if (r < N) {
                if (tok) {
                    int ti = r * T + teff;
                    int tv = is64 ? tok[2 * (size_t)ti] : tok[ti];
                    gxp[idx] = PV + ((size_t)d * VOCAB + tv) * G3;
                } else {
                    gxp[idx] = GX + ((size_t)d * N * T + (size_t)r * T + teff) * G3;
                }
            } else gxp[idx] = PV ? PV : GX;
        }

        float acc[3][4][4];
#pragma unroll
        for (int i = 0; i < 3; ++i)
#pragma unroll
            for (int j = 0; j < 4; ++j)
#pragma unroll
                for (int k = 0; k < 4; ++k) acc[i][j][k] = 0.f;

        if (t > 0) {   // step 0: Hin == 0 -> Gh == 0, skip entirely
            uint4 ph[8];
#pragma unroll
            for (int it = 0; it < 8; ++it) {
                int rl = srow + it * 4;
                ph[it] = make_uint4(0u, 0u, 0u, 0u);
                if (n0 + rl < N)
                    ph[it] = *(const uint4*)(Hin + (size_t)(d * N + n0 + rl) * HD + sq * 4);
            }

            for (int k0i = 0; k0i < 8; ++k0i) {
#pragma unroll
                for (int it = 0; it < 8; ++it)
                    *(uint4*)(&Hsm[srow + it * 4][sq * 4]) = ph[it];  // raw tf32 bits
                barpair(barId);

                if (k0i < 7) {
                    int k0 = (k0i + 1) * 32;
#pragma unroll
                    for (int it = 0; it < 8; ++it) {
                        int rl = srow + it * 4;
                        ph[it] = make_uint4(0u, 0u, 0u, 0u);
                        if (n0 + rl < N)
                            ph[it] = *(const uint4*)(Hin + (size_t)(d * N + n0 + rl) * HD + k0 + sq * 4);
                    }
                }

                unsigned kwo = (unsigned)(k0i * 128);
#pragma unroll
                for (int ks = 0; ks < 4; ++ks) {
                    unsigned kbo = (unsigned)(ks * 32);
                    unsigned a[4][4];
#pragma unroll
                    for (int mt = 0; mt < 4; ++mt)
                        ldsm4(a[mt][0], a[mt][1], a[mt][2], a[mt][3], aAddr[mt] + kbo);
                    unsigned b00, b01, b10, b11, b20, b21;
                    ldsm4(b00, b01, b10, b11, bAddr01 + kwo + kbo);
                    ldsm2(b20, b21, bAddr2 + kwo + kbo);
#pragma unroll
                    for (int mt = 0; mt < 4; ++mt) {
                        mma8(acc[0][mt], a[mt][0], a[mt][1], a[mt][2], a[mt][3], b00, b01);
                        mma8(acc[1][mt], a[mt][0], a[mt][1], a[mt][2], a[mt][3], b10, b11);
                        mma8(acc[2][mt], a[mt][0], a[mt][1], a[mt][2], a[mt][3], b20, b21);
                    }
                }
                if (k0i < 7) barpair(barId);   // readers done before next STS
            }
        }

        // ---- gate math epilogue: 8 instances in 2 phases of 4 ----
#pragma unroll
        for (int phx = 0; phx < 2; ++phx) {
            float2 GR[4], GZ[4], GN[4], HH[4];
            bool val[4];
#pragma unroll
            for (int i = 0; i < 4; ++i) {
                int idx = phx * 4 + i;
                int r = rowi[idx];
                val[i] = (r < N);
                GR[i] = GZ[i] = GN[i] = HH[i] = make_float2(0.f, 0.f);
                if (val[i]) {
                    const float* gxrow = gxp[idx];
                    GR[i] = *(const float2*)(gxrow + cc);
                    GZ[i] = *(const float2*)(gxrow + 256 + cc);
                    GN[i] = *(const float2*)(gxrow + 512 + cc);
                    if (t > 0) HH[i] = *(const float2*)(Hin + (size_t)(d * N + r) * HD + cc);
                }
            }
#pragma unroll
            for (int i = 0; i < 4; ++i) {
                if (!val[i]) continue;
                int idx = phx * 4 + i;
                int mt = idx >> 1, half = idx & 1;
                float aR0 = acc[0][mt][half * 2 + 0], aR1 = acc[0][mt][half * 2 + 1];
                float aZ0 = acc[1][mt][half * 2 + 0], aZ1 = acc[1][mt][half * 2 + 1];
                float aN0 = acc[2][mt][half * 2 + 0], aN1 = acc[2][mt][half * 2 + 1];

                float r0 = fsigm(GR[i].x + aR0 + br2.x);
                float r1 = fsigm(GR[i].y + aR1 + br2.y);
                float z0 = fsigm(GZ[i].x + aZ0 + bz2.x);
                float z1 = fsigm(GZ[i].y + aZ1 + bz2.y);
                float n0v = ftanh(GN[i].x + r0 * (aN0 + bn2.x));
                float n1v = ftanh(GN[i].y + r1 * (aN1 + bn2.y));

                float2 o;
                o.x = n0v + z0 * (HH[i].x - n0v);
                o.y = n1v + z1 * (HH[i].y - n1v);
                *(float2*)(Hout + (size_t)(d * N + rowi[idx]) * HD + cc) = o;
            }
        }

        if (t + 1 < T) gbar(bid, 16, (unsigned)(t + 1));
    }
}

// ---------------- FC head: Linear(256->128) -> SELU -> Linear(128->1) on (X+X2) ----------------
__global__ void fc_head(const float* __restrict__ X, const float* __restrict__ X2,
                        const float* __restrict__ W1, const float* __restrict__ b1,
                        const float* __restrict__ W2, const float* __restrict__ b2,
                        float* __restrict__ out)
{
    int row = blockIdx.x;
    int h = threadIdx.x;  // 128 threads
    const float* x  = X  + (size_t)row * HD;
    const float* x2 = X2 + (size_t)row * HD;
    const float* w  = W1 + (size_t)h * HD;
    float s = 0.f;
#pragma unroll 8
    for (int k = 0; k < HD; k += 4) {
        float4 xv = *(const float4*)(x + k);
        float4 yv = *(const float4*)(x2 + k);
        float4 wv = *(const float4*)(w + k);
        s += (xv.x + yv.x) * wv.x + (xv.y + yv.y) * wv.y
           + (xv.z + yv.z) * wv.z + (xv.w + yv.w) * wv.w;
    }
    s += b1[h];
    const float SC = 1.0507009873554805f, AL = 1.6732632423543772f;
    float selu = SC * (s > 0.f ? s : AL * expm1f(s));
    float v = selu * W2[h];
    __shared__ float red[128];
    red[h] = v; __syncthreads();
    for (int st = 64; st > 0; st >>= 1) {
        if (h < st) red[h] += red[h + st];
        __syncthreads();
    }
    if (h == 0) out[row] = red[0] + b2[0];
}

// ---------------- launch ----------------
extern "C" void kernel_launch(void* const* d_in, const int* in_sizes, int n_in,
                              void* d_out, int out_size)
{
    const int*   tok   = (const int*)  d_in[0];
    const float* emb   = (const float*)d_in[1];
    const float* wWih  = (const float*)d_in[2];
    const float* wWhh  = (const float*)d_in[3];
    const float* wbih  = (const float*)d_in[4];
    const float* wbhh  = (const float*)d_in[5];
    const float* sWih  = (const float*)d_in[6];
    const float* sWhh  = (const float*)d_in[7];
    const float* sbih  = (const float*)d_in[8];
    const float* sbhh  = (const float*)d_in[9];
    const float* rWih  = (const float*)d_in[10];
    const float* rWhh  = (const float*)d_in[11];
    const float* rbih  = (const float*)d_in[12];
    const float* rbhh  = (const float*)d_in[13];
    const float* rfcW1 = (const float*)d_in[14];
    const float* rfcb1 = (const float*)d_in[15];
    const float* rfcW2 = (const float*)d_in[16];
    const float* rfcb2 = (const float*)d_in[17];
    const float* pfcW1 = (const float*)d_in[18];
    const float* pfcb1 = (const float*)d_in[19];
    const float* pfcW2 = (const float*)d_in[20];
    const float* pfcb2 = (const float*)d_in[21];
    float* out = (float*)d_out;

    static bool attr_set = false;
    if (!attr_set) {
        cudaFuncSetAttribute(gru_scan, cudaFuncAttributeMaxDynamicSharedMemorySize,
                             SCAN_SMEM_BYTES);
        cudaFuncSetAttribute(gemm_proj_mma, cudaFuncAttributeMaxDynamicSharedMemorySize,
                             GEMM_SMEM_BYTES);
        attr_set = true;
    }

    float *pv, *gxs, *gxr, *hwB, *hsB, *hrB;
    cudaGetSymbolAddress((void**)&pv,  g_PV);
    cudaGetSymbolAddress((void**)&gxs, g_GXs);
    cudaGetSymbolAddress((void**)&gxr, g_GXr);
    cudaGetSymbolAddress((void**)&hwB, g_Hw);
    cudaGetSymbolAddress((void**)&hsB, g_Hs);
    cudaGetSymbolAddress((void**)&hrB, g_Hr);

    float* hw1 = hwB + (size_t)2 * NW * HD;
    float* hs1 = hsB + (size_t)2 * NS * HD;
    float* hr1 = hrB + (size_t)2 * NR * HD;

    kinit_bar<<<1, NBAR * BPAD>>>();

    // project full vocabulary once per direction: PV = emb @ Wih^T + bih
    gemm_proj_mma<<<dim3((VOCAB + 127) / 128, G3 / 64, 2), 256, GEMM_SMEM_BYTES>>>(
        emb, nullptr, VOCAB, wWih, wbih, pv);

    // word-level scan (T=32)
    gru_scan<<<dim3(NW / 256, 16, 2), 256, SCAN_SMEM_BYTES>>>(
        hwB, hw1, wWhh, wbhh, nullptr, pv, tok, NW, TW, 0);
    float* hwF = (TW & 1) ? hw1 : hwB;

    // sentence-level: project (hf+hb fused) + scan (T=16)
    gemm_proj_mma<<<dim3((NW + 127) / 128, G3 / 64, 2), 256, GEMM_SMEM_BYTES>>>(
        hwF, hwF + (size_t)NW * HD, NW, sWih, sbih, gxs);
    gru_scan<<<dim3(1, 16, 2), 256, SCAN_SMEM_BYTES>>>(
        hsB, hs1, sWhh, sbhh, gxs, nullptr, nullptr, NS, TS, 16);
    float* hsF = (TS & 1) ? hs1 : hsB;

    // review-star head -> out[8..135]
    fc_head<<<NS, 128>>>(hsF, hsF + (size_t)NS * HD, rfcW1, rfcb1, rfcW2, rfcb2, out + NR);

    // review-level (business) biGRU: project (fused sum) + scan (T=16)
    gemm_proj_mma<<<dim3(1, G3 / 64, 2), 256, GEMM_SMEM_BYTES>>>(
        hsF, hsF + (size_t)NS * HD, NS, rWih, rbih, gxr);
    gru_scan<<<dim3(1, 16, 2), 256, SCAN_SMEM_BYTES>>>(
        hrB, hr1, rWhh, rbhh, gxr, nullptr, nullptr, NR, TR, 18);
    float* hrF = (TR & 1) ? hr1 : hrB;

    // business head -> out[0..7]
    fc_head<<<NR, 128>>>(hrF, hrF + (size_t)NR * HD, pfcW1, pfcb1, pfcW2, pfcb2, out);

    (void)in_sizes; (void)n_in; (void)out_size;
}

// round 12
// speedup vs baseline: 1.4279x; 1.2787x over previous
#include <cuda_runtime.h>
#include <cuda_fp16.h>
#include <cstdint>

// ---------------- problem constants ----------------
#define HD   256      // hidden / embedding dim
#define G3   768      // 3*H gate dim
#define VOCAB 30000
#define NW   2048     // word-level sequences (B*R*S)
#define TW   32       // word-level timesteps (W)
#define NS   128      // sentence-level sequences (B*R)
#define TS   16       // sentence-level timesteps (S)
#define NR   8        // review-level sequences (B)
#define TR   16       // review-level timesteps (R)

#define WH   264      // Wres row stride in halfs (528B ≡ 16 mod 128 -> conflict-free)
#define HS2  40       // H/A/B chunk row stride in halfs (80B -> conflict-free ldsm)

// scan smem (halfs): Wres[48*WH] + Hsm[2][256][HS2]
#define SCAN_SMEM_BYTES ((48*WH + 2*256*HS2) * 2)
// gemm smem (halfs): As[2][128][HS2] + Bs[2][64][HS2]
#define GEMM_SMEM_BYTES ((2*128*HS2 + 2*64*HS2) * 2)

#define NBAR 20       // word 0..15, sentence 16..17, review 18..19
#define BPAD 32       // barrier slot padding (128B)

// ---------------- scratch (static device globals; no runtime alloc) ----------------
__device__ float g_PV [(size_t)2*VOCAB*G3];        // projected vocab per dir
__device__ float g_GXs[(size_t)2*NS*TS*G3];        // sentence-level gx
__device__ float g_GXr[(size_t)2*NR*TR*G3];        // review-level gx
__device__ float g_Hw [2][(size_t)2*NW*HD];        // ping-pong hidden, word
__device__ float g_Hs [2][(size_t)2*NS*HD];        // sentence
__device__ float g_Hr [2][(size_t)2*NR*HD];        // review

// grid-barrier state: one padded slot per (scan, dir, rowgroup)
__device__ unsigned g_cnt[NBAR * BPAD];
__device__ volatile unsigned g_phase[NBAR * BPAD];

// ---------------- helpers ----------------
__device__ __forceinline__ float fsigm(float x) {
    float e = __expf(-x);
    return __fdividef(1.f, 1.f + e);
}
__device__ __forceinline__ float ftanh(float x) {
    float ax = fabsf(x);
    float e = __expf(-2.f * ax);
    float r = __fdividef(1.f - e, 1.f + e);
    return copysignf(r, x);
}

__device__ __forceinline__ unsigned f2h2u(float lo, float hi) {
    __half2 h = __floats2half2_rn(lo, hi);
    return *(unsigned*)&h;
}

__device__ __forceinline__ void mma16(float* d,
                                      unsigned a0, unsigned a1, unsigned a2, unsigned a3,
                                      unsigned b0, unsigned b1) {
    asm volatile(
        "mma.sync.aligned.m16n8k16.row.col.f32.f16.f16.f32 "
        "{%0,%1,%2,%3},{%4,%5,%6,%7},{%8,%9},{%0,%1,%2,%3};"
        : "+f"(d[0]), "+f"(d[1]), "+f"(d[2]), "+f"(d[3])
        : "r"(a0), "r"(a1), "r"(a2), "r"(a3), "r"(b0), "r"(b1));
}

__device__ __forceinline__ void ldsm4(unsigned& r0, unsigned& r1, unsigned& r2, unsigned& r3,
                                      unsigned addr) {
    asm volatile("ldmatrix.sync.aligned.m8n8.x4.shared.b16 {%0,%1,%2,%3}, [%4];"
                 : "=r"(r0), "=r"(r1), "=r"(r2), "=r"(r3) : "r"(addr));
}
__device__ __forceinline__ void ldsm2(unsigned& r0, unsigned& r1, unsigned addr) {
    asm volatile("ldmatrix.sync.aligned.m8n8.x2.shared.b16 {%0,%1}, [%2];"
                 : "=r"(r0), "=r"(r1) : "r"(addr));
}

// 2-warp named barrier (64 threads), ids 1..4
__device__ __forceinline__ void barpair(int id) {
    asm volatile("bar.sync %0, 64;" :: "r"(id) : "memory");
}

__global__ void kinit_bar() {
    int i = threadIdx.x;
    if (i < NBAR * BPAD) { g_cnt[i] = 0; g_phase[i] = 0; }
}

// software grid barrier over an nCTA-member group (slot = id*BPAD)
__device__ __forceinline__ void gbar(int id, unsigned nCTA, unsigned target) {
    __syncthreads();
    if (threadIdx.x == 0) {
        __threadfence();
        unsigned* cnt = &g_cnt[id * BPAD];
        unsigned old = atomicAdd(cnt, 1u);
        if (old == nCTA - 1u) {
            *cnt = 0u;
            __threadfence();
            g_phase[id * BPAD] = target;
        } else {
            while (g_phase[id * BPAD] < target) __nanosleep(32);
        }
        __threadfence();
    }
    __syncthreads();
}

// ---------------- FP16 GEMM: C[d][M,768] = (A(+A2))[M,256] @ W[d][768,256]^T + bias[d] ----------------
// CTA 128(m) x 64(n), 8 warps 4m x 2n, warp tile 32x32 (mt=2, nt=4); double-buffered.
__global__ __launch_bounds__(256, 2)
void gemm_proj_mma(const float* __restrict__ A, const float* __restrict__ A2, int M,
                   const float* __restrict__ W, const float* __restrict__ bias,
                   float* __restrict__ C)
{
    extern __shared__ __half gsm[];
    __half* As = gsm;                   // [2][128][HS2]
    __half* Bs = gsm + 2 * 128 * HS2;   // [2][64][HS2]

    int d = blockIdx.z;
    const float* Wd = W    + (size_t)d * G3 * HD;
    const float* bd = bias + (size_t)d * G3;
    float*       Cd = C    + (size_t)d * M * G3;

    int m0 = blockIdx.x * 128;
    int n0 = blockIdx.y * 64;

    int tid = threadIdx.x, lane = tid & 31, wid = tid >> 5;
    int wm = wid & 3, wn = wid >> 2;
    int RB = wm * 32, CB = wn * 32;
    int g = lane >> 2, c = lane & 3;

    int l7 = lane & 7, ts = lane >> 3;
    unsigned sAs = (unsigned)__cvta_generic_to_shared(As);
    unsigned sBs = (unsigned)__cvta_generic_to_shared(Bs);

    // A frag tiles: (rows 0-7 klo),(rows 8-15 klo),(rows 0-7 khi),(rows 8-15 khi)
    unsigned aAddr[2];
#pragma unroll
    for (int mt = 0; mt < 2; ++mt)
        aAddr[mt] = sAs + (unsigned)(((RB + mt * 16 + l7 + (ts & 1) * 8) * HS2
                                      + (ts >> 1) * 8) * 2);
    // B frag tiles for ldsm4 #p: (n=2p klo),(n=2p khi),(n=2p+1 klo),(n=2p+1 khi)
    unsigned bAddr[2];
#pragma unroll
    for (int p = 0; p < 2; ++p)
        bAddr[p] = sBs + (unsigned)(((CB + (2 * p + (ts >> 1)) * 8 + l7) * HS2
                                     + (ts & 1) * 8) * 2);

    float acc[2][4][4];
#pragma unroll
    for (int i = 0; i < 2; ++i)
#pragma unroll
        for (int j = 0; j < 4; ++j)
#pragma unroll
            for (int k = 0; k < 4; ++k) acc[i][j][k] = 0.f;

    int lr = tid >> 3, lq = tid & 7;

    float4 pa[4], pw[2];
#pragma unroll
    for (int it = 0; it < 4; ++it) {
        int r = lr + it * 32;
        pa[it] = make_float4(0.f, 0.f, 0.f, 0.f);
        if (m0 + r < M) {
            size_t off = (size_t)(m0 + r) * HD + lq * 4;
            pa[it] = *(const float4*)(A + off);
            if (A2) {
                float4 b = *(const float4*)(A2 + off);
                pa[it].x += b.x; pa[it].y += b.y; pa[it].z += b.z; pa[it].w += b.w;
            }
        }
    }
#pragma unroll
    for (int it = 0; it < 2; ++it) {
        int r = lr + it * 32;
        pw[it] = *(const float4*)(Wd + (size_t)(n0 + r) * HD + lq * 4);
    }
#pragma unroll
    for (int it = 0; it < 4; ++it) {
        int r = lr + it * 32;
        *(uint2*)(As + (size_t)r * HS2 + lq * 4) =
            make_uint2(f2h2u(pa[it].x, pa[it].y), f2h2u(pa[it].z, pa[it].w));
    }
#pragma unroll
    for (int it = 0; it < 2; ++it) {
        int r = lr + it * 32;
        *(uint2*)(Bs + (size_t)r * HS2 + lq * 4) =
            make_uint2(f2h2u(pw[it].x, pw[it].y), f2h2u(pw[it].z, pw[it].w));
    }
    __syncthreads();

    for (int k0i = 0; k0i < 8; ++k0i) {
        int cur = k0i & 1;
        if (k0i < 7) {
            int k0 = (k0i + 1) * 32;
#pragma unroll
            for (int it = 0; it < 4; ++it) {
                int r = lr + it * 32;
                pa[it] = make_float4(0.f, 0.f, 0.f, 0.f);
                if (m0 + r < M) {
                    size_t off = (size_t)(m0 + r) * HD + k0 + lq * 4;
                    pa[it] = *(const float4*)(A + off);
                    if (A2) {
                        float4 b = *(const float4*)(A2 + off);
                        pa[it].x += b.x; pa[it].y += b.y; pa[it].z += b.z; pa[it].w += b.w;
                    }
                }
            }
#pragma unroll
            for (int it = 0; it < 2; ++it) {
                int r = lr + it * 32;
                pw[it] = *(const float4*)(Wd + (size_t)(n0 + r) * HD + k0 + lq * 4);
            }
        }

        unsigned aBuf = (unsigned)(cur * 128 * HS2 * 2);
        unsigned bBuf = (unsigned)(cur * 64 * HS2 * 2);
#pragma unroll
        for (int ks = 0; ks < 2; ++ks) {
            unsigned kbo = (unsigned)(ks * 32);   // 16 halfs
            unsigned a[2][4];
#pragma unroll
            for (int mt = 0; mt < 2; ++mt)
                ldsm4(a[mt][0], a[mt][1], a[mt][2], a[mt][3], aAddr[mt] + aBuf + kbo);
            unsigned b[4][2];
#pragma unroll
            for (int p = 0; p < 2; ++p)
                ldsm4(b[2*p][0], b[2*p][1], b[2*p+1][0], b[2*p+1][1], bAddr[p] + bBuf + kbo);
#pragma unroll
            for (int nt = 0; nt < 4; ++nt)
#pragma unroll
                for (int mt = 0; mt < 2; ++mt)
                    mma16(acc[mt][nt], a[mt][0], a[mt][1], a[mt][2], a[mt][3],
                          b[nt][0], b[nt][1]);
        }

        if (k0i < 7) {
            __half* An = As + (size_t)(cur ^ 1) * 128 * HS2;
            __half* Bn = Bs + (size_t)(cur ^ 1) * 64 * HS2;
#pragma unroll
            for (int it = 0; it < 4; ++it) {
                int r = lr + it * 32;
                *(uint2*)(An + (size_t)r * HS2 + lq * 4) =
                    make_uint2(f2h2u(pa[it].x, pa[it].y), f2h2u(pa[it].z, pa[it].w));
            }
#pragma unroll
            for (int it = 0; it < 2; ++it) {
                int r = lr + it * 32;
                *(uint2*)(Bn + (size_t)r * HS2 + lq * 4) =
                    make_uint2(f2h2u(pw[it].x, pw[it].y), f2h2u(pw[it].z, pw[it].w));
            }
        }
        __syncthreads();
    }

#pragma unroll
    for (int nt = 0; nt < 4; ++nt) {
        int col = n0 + CB + nt * 8 + 2 * c;
        float2 bb = *(const float2*)(bd + col);
#pragma unroll
        for (int mt = 0; mt < 2; ++mt) {
            int row0 = m0 + RB + mt * 16 + g;
            if (row0 < M) {
                float2 o = make_float2(acc[mt][nt][0] + bb.x, acc[mt][nt][1] + bb.y);
                *(float2*)(Cd + (size_t)row0 * G3 + col) = o;
            }
            int row1 = row0 + 8;
            if (row1 < M) {
                float2 o = make_float2(acc[mt][nt][2] + bb.x, acc[mt][nt][3] + bb.y);
                *(float2*)(Cd + (size_t)row1 * G3 + col) = o;
            }
        }
    }
}

// ---------------- persistent fused GRU scan (fp16 MMA) ----------------
// CTA: 256 rows x 16 j-cols x 3 gates; W resident fp16; H staged fp16 slab-local
// into a double-buffered chunk tile (one 2-warp named barrier per chunk).
__global__ __launch_bounds__(256, 2)
void gru_scan(float* __restrict__ H0, float* __restrict__ H1,
              const float* __restrict__ Whh,   // [2][768][256]
              const float* __restrict__ bhh,   // [2][768]
              const float* __restrict__ GX,    // [2][N*T][768] or nullptr
              const float* __restrict__ PV,    // [2][VOCAB][768] or nullptr
              const int*   __restrict__ tok,   // tokens or nullptr
              int N, int T, int barBase)
{
    extern __shared__ __half smemh[];
    __half* Wres = smemh;                        // [48][WH]
    __half* Hsm  = smemh + 48 * WH;              // [2][256][HS2]

    int d  = blockIdx.z;
    int n0 = blockIdx.x * 256;
    int j0 = blockIdx.y * 16;
    int bid = barBase + d * gridDim.x + blockIdx.x;

    const float* Wd = Whh + (size_t)d * G3 * HD;

    int tid = threadIdx.x, lane = tid & 31, wid = tid >> 5;
    int wm = wid & 3, wn = wid >> 2;
    int RB = wm * 64, CB = wn * 8;
    int g = lane >> 2, c = lane & 3;

    // ---- load resident W slice (fp16 RN once) ----
    for (int idx = tid; idx < 48 * 64; idx += 256) {
        int row = idx >> 6;
        int c4  = idx & 63;
        int gt = row >> 4, j = row & 15;
        float4 v = *(const float4*)(Wd + (size_t)(gt * 256 + j0 + j) * HD + c4 * 4);
        *(uint2*)(Wres + (size_t)row * WH + c4 * 4) =
            make_uint2(f2h2u(v.x, v.y), f2h2u(v.z, v.w));
    }
    __syncthreads();

    int l7 = lane & 7, ts = lane >> 3;
    unsigned sH = (unsigned)__cvta_generic_to_shared(Hsm);
    unsigned sW = (unsigned)__cvta_generic_to_shared(Wres);

    unsigned aAddr[4];
#pragma unroll
    for (int mt = 0; mt < 4; ++mt)
        aAddr[mt] = sH + (unsigned)(((RB + mt * 16 + l7 + (ts & 1) * 8) * HS2
                                     + (ts >> 1) * 8) * 2);
    // gates 0,1 via one ldsm4; gate 2 via ldsm2
    unsigned bAddr01 = sW + (unsigned)((((ts >> 1) * 16 + CB + l7) * WH + (ts & 1) * 8) * 2);
    unsigned bAddr2  = sW + (unsigned)(((32 + CB + l7) * WH + (ts & 1) * 8) * 2);

    bool is64 = false;
    if (tok) is64 = (tok[1] == 0) & (tok[3] == 0) & (tok[5] == 0) & (tok[7] == 0);

    int cc = j0 + CB + 2 * c;
    float2 br2 = *(const float2*)(bhh + (size_t)d * G3 + cc);
    float2 bz2 = *(const float2*)(bhh + (size_t)d * G3 + 256 + cc);
    float2 bn2 = *(const float2*)(bhh + (size_t)d * G3 + 512 + cc);

    // slab-local staging: warp pair (wm, wm+4) owns rows [wm*64, +64)
    int srow = wm * 64 + wn * 32 + (lane >> 3);  // + it*4
    int sq   = lane & 7;
    int barId = wm + 1;

    int rowi[8];
#pragma unroll
    for (int idx = 0; idx < 8; ++idx) {
        int mt = idx >> 1, half = idx & 1;
        rowi[idx] = n0 + RB + mt * 16 + g + half * 8;
    }

    for (int t = 0; t < T; ++t) {
        const float* Hin  = (t & 1) ? H1 : H0;
        float*       Hout = (t & 1) ? H0 : H1;
        int teff = d ? (T - 1 - t) : t;

        const float* gxp[8];
#pragma unroll
        for (int idx = 0; idx < 8; ++idx) {
            int r = rowi[idx];
            if (r < N) {
                if (tok) {
                    int ti = r * T + teff;
                    int tv = is64 ? tok[2 * (size_t)ti] : tok[ti];
                    gxp[idx] = PV + ((size_t)d * VOCAB + tv) * G3;
                } else {
                    gxp[idx] = GX + ((size_t)d * N * T + (size_t)r * T + teff) * G3;
                }
            } else gxp[idx] = PV ? PV : GX;
        }

        float acc[3][4][4];
#pragma unroll
        for (int i = 0; i < 3; ++i)
#pragma unroll
            for (int j = 0; j < 4; ++j)
#pragma unroll
                for (int k = 0; k < 4; ++k) acc[i][j][k] = 0.f;

        if (t > 0) {   // step 0: Hin == 0 -> Gh == 0
            float4 ph[8];
#pragma unroll
            for (int it = 0; it < 8; ++it) {
                int rl = srow + it * 4;
                ph[it] = make_float4(0.f, 0.f, 0.f, 0.f);
                if (n0 + rl < N)
                    ph[it] = *(const float4*)(Hin + (size_t)(d * N + n0 + rl) * HD + sq * 4);
            }

            for (int k0i = 0; k0i < 8; ++k0i) {
                __half* buf = Hsm + (size_t)(k0i & 1) * 256 * HS2;
#pragma unroll
                for (int it = 0; it < 8; ++it)
                    *(uint2*)(buf + (size_t)(srow + it * 4) * HS2 + sq * 4) =
                        make_uint2(f2h2u(ph[it].x, ph[it].y), f2h2u(ph[it].z, ph[it].w));
                barpair(barId);

                if (k0i < 7) {
                    int k0 = (k0i + 1) * 32;
#pragma unroll
                    for (int it = 0; it < 8; ++it) {
                        int rl = srow + it * 4;
                        ph[it] = make_float4(0.f, 0.f, 0.f, 0.f);
                        if (n0 + rl < N)
                            ph[it] = *(const float4*)(Hin + (size_t)(d * N + n0 + rl) * HD + k0 + sq * 4);
                    }
                }

                unsigned hbuf = (unsigned)((k0i & 1) * 256 * HS2 * 2);
                unsigned kwo  = (unsigned)(k0i * 64);   // 32 halfs per chunk in W
#pragma unroll
                for (int ks = 0; ks < 2; ++ks) {
                    unsigned kbo = (unsigned)(ks * 32); // 16 halfs
                    unsigned a[4][4];
#pragma unroll
                    for (int mt = 0; mt < 4; ++mt)
                        ldsm4(a[mt][0], a[mt][1], a[mt][2], a[mt][3],
                              aAddr[mt] + hbuf + kbo);
                    unsigned b00, b01, b10, b11, b20, b21;
                    ldsm4(b00, b01, b10, b11, bAddr01 + kwo + kbo);
                    ldsm2(b20, b21, bAddr2 + kwo + kbo);
#pragma unroll
                    for (int mt = 0; mt < 4; ++mt) {
                        mma16(acc[0][mt], a[mt][0], a[mt][1], a[mt][2], a[mt][3], b00, b01);
                        mma16(acc[1][mt], a[mt][0], a[mt][1], a[mt][2], a[mt][3], b10, b11);
                        mma16(acc[2][mt], a[mt][0], a[mt][1], a[mt][2], a[mt][3], b20, b21);
                    }
                }
            }
        }

        // ---- gate math epilogue: 8 instances in 2 phases of 4 ----
#pragma unroll
        for (int phx = 0; phx < 2; ++phx) {
            float2 GR[4], GZ[4], GN[4], HH[4];
            bool val[4];
#pragma unroll
            for (int i = 0; i < 4; ++i) {
                int idx = phx * 4 + i;
                int r = rowi[idx];
                val[i] = (r < N);
                GR[i] = GZ[i] = GN[i] = HH[i] = make_float2(0.f, 0.f);
                if (val[i]) {
                    const float* gxrow = gxp[idx];
                    GR[i] = *(const float2*)(gxrow + cc);
                    GZ[i] = *(const float2*)(gxrow + 256 + cc);
                    GN[i] = *(const float2*)(gxrow + 512 + cc);
                    if (t > 0) HH[i] = *(const float2*)(Hin + (size_t)(d * N + r) * HD + cc);
                }
            }
#pragma unroll
            for (int i = 0; i < 4; ++i) {
                if (!val[i]) continue;
                int idx = phx * 4 + i;
                int mt = idx >> 1, half = idx & 1;
                float aR0 = acc[0][mt][half * 2 + 0], aR1 = acc[0][mt][half * 2 + 1];
                float aZ0 = acc[1][mt][half * 2 + 0], aZ1 = acc[1][mt][half * 2 + 1];
                float aN0 = acc[2][mt][half * 2 + 0], aN1 = acc[2][mt][half * 2 + 1];

                float r0 = fsigm(GR[i].x + aR0 + br2.x);
                float r1 = fsigm(GR[i].y + aR1 + br2.y);
                float z0 = fsigm(GZ[i].x + aZ0 + bz2.x);
                float z1 = fsigm(GZ[i].y + aZ1 + bz2.y);
                float n0v = ftanh(GN[i].x + r0 * (aN0 + bn2.x));
                float n1v = ftanh(GN[i].y + r1 * (aN1 + bn2.y));

                float2 o;
                o.x = n0v + z0 * (HH[i].x - n0v);
                o.y = n1v + z1 * (HH[i].y - n1v);
                *(float2*)(Hout + (size_t)(d * N + rowi[idx]) * HD + cc) = o;
            }
        }

        if (t + 1 < T) gbar(bid, 16, (unsigned)(t + 1));
    }
}

// ---------------- FC head: Linear(256->128) -> SELU -> Linear(128->1) on (X+X2) ----------------
__global__ void fc_head(const float* __restrict__ X, const float* __restrict__ X2,
                        const float* __restrict__ W1, const float* __restrict__ b1,
                        const float* __restrict__ W2, const float* __restrict__ b2,
                        float* __restrict__ out)
{
    int row = blockIdx.x;
    int h = threadIdx.x;  // 128 threads
    const float* x  = X  + (size_t)row * HD;
    const float* x2 = X2 + (size_t)row * HD;
    const float* w  = W1 + (size_t)h * HD;
    float s = 0.f;
#pragma unroll 8
    for (int k = 0; k < HD; k += 4) {
        float4 xv = *(const float4*)(x + k);
        float4 yv = *(const float4*)(x2 + k);
        float4 wv = *(const float4*)(w + k);
        s += (xv.x + yv.x) * wv.x + (xv.y + yv.y) * wv.y
           + (xv.z + yv.z) * wv.z + (xv.w + yv.w) * wv.w;
    }
    s += b1[h];
    const float SC = 1.0507009873554805f, AL = 1.6732632423543772f;
    float selu = SC * (s > 0.f ? s : AL * expm1f(s));
    float v = selu * W2[h];
    __shared__ float red[128];
    red[h] = v; __syncthreads();
    for (int st = 64; st > 0; st >>= 1) {
        if (h < st) red[h] += red[h + st];
        __syncthreads();
    }
    if (h == 0) out[row] = red[0] + b2[0];
}

// ---------------- launch ----------------
extern "C" void kernel_launch(void* const* d_in, const int* in_sizes, int n_in,
                              void* d_out, int out_size)
{
    const int*   tok   = (const int*)  d_in[0];
    const float* emb   = (const float*)d_in[1];
    const float* wWih  = (const float*)d_in[2];
    const float* wWhh  = (const float*)d_in[3];
    const float* wbih  = (const float*)d_in[4];
    const float* wbhh  = (const float*)d_in[5];
    const float* sWih  = (const float*)d_in[6];
    const float* sWhh  = (const float*)d_in[7];
    const float* sbih  = (const float*)d_in[8];
    const float* sbhh  = (const float*)d_in[9];
    const float* rWih  = (const float*)d_in[10];
    const float* rWhh  = (const float*)d_in[11];
    const float* rbih  = (const float*)d_in[12];
    const float* rbhh  = (const float*)d_in[13];
    const float* rfcW1 = (const float*)d_in[14];
    const float* rfcb1 = (const float*)d_in[15];
    const float* rfcW2 = (const float*)d_in[16];
    const float* rfcb2 = (const float*)d_in[17];
    const float* pfcW1 = (const float*)d_in[18];
    const float* pfcb1 = (const float*)d_in[19];
    const float* pfcW2 = (const float*)d_in[20];
    const float* pfcb2 = (const float*)d_in[21];
    float* out = (float*)d_out;

    static bool attr_set = false;
    if (!attr_set) {
        cudaFuncSetAttribute(gru_scan, cudaFuncAttributeMaxDynamicSharedMemorySize,
                             SCAN_SMEM_BYTES);
        cudaFuncSetAttribute(gemm_proj_mma, cudaFuncAttributeMaxDynamicSharedMemorySize,
                             GEMM_SMEM_BYTES);
        attr_set = true;
    }

    float *pv, *gxs, *gxr, *hwB, *hsB, *hrB;
    cudaGetSymbolAddress((void**)&pv,  g_PV);
    cudaGetSymbolAddress((void**)&gxs, g_GXs);
    cudaGetSymbolAddress((void**)&gxr, g_GXr);
    cudaGetSymbolAddress((void**)&hwB, g_Hw);
    cudaGetSymbolAddress((void**)&hsB, g_Hs);
    cudaGetSymbolAddress((void**)&hrB, g_Hr);

    float* hw1 = hwB + (size_t)2 * NW * HD;
    float* hs1 = hsB + (size_t)2 * NS * HD;
    float* hr1 = hrB + (size_t)2 * NR * HD;

    kinit_bar<<<1, NBAR * BPAD>>>();

    // project full vocabulary once per direction: PV = emb @ Wih^T + bih
    gemm_proj_mma<<<dim3((VOCAB + 127) / 128, G3 / 64, 2), 256, GEMM_SMEM_BYTES>>>(
        emb, nullptr, VOCAB, wWih, wbih, pv);

    // word-level scan (T=32)
    gru_scan<<<dim3(NW / 256, 16, 2), 256, SCAN_SMEM_BYTES>>>(
        hwB, hw1, wWhh, wbhh, nullptr, pv, tok, NW, TW, 0);
    float* hwF = (TW & 1) ? hw1 : hwB;

    // sentence-level: project (hf+hb fused) + scan (T=16)
    gemm_proj_mma<<<dim3((NW + 127) / 128, G3 / 64, 2), 256, GEMM_SMEM_BYTES>>>(
        hwF, hwF + (size_t)NW * HD, NW, sWih, sbih, gxs);
    gru_scan<<<dim3(1, 16, 2), 256, SCAN_SMEM_BYTES>>>(
        hsB, hs1, sWhh, sbhh, gxs, nullptr, nullptr, NS, TS, 16);
    float* hsF = (TS & 1) ? hs1 : hsB;

    // review-star head -> out[8..135]
    fc_head<<<NS, 128>>>(hsF, hsF + (size_t)NS * HD, rfcW1, rfcb1, rfcW2, rfcb2, out + NR);

    // review-level (business) biGRU: project (fused sum) + scan (T=16)
    gemm_proj_mma<<<dim3(1, G3 / 64, 2), 256, GEMM_SMEM_BYTES>>>(
        hsF, hsF + (size_t)NS * HD, NS, rWih, rbih, gxr);
    gru_scan<<<dim3(1, 16, 2), 256, SCAN_SMEM_BYTES>>>(
        hrB, hr1, rWhh, rbhh, gxr, nullptr, nullptr, NR, TR, 18);
    float* hrF = (TR & 1) ? hr1 : hrB;

    // business head -> out[0..7]
    fc_head<<<NR, 128>>>(hrF, hrF + (size_t)NR * HD, pfcW1, pfcb1, pfcW2, pfcb2, out);

    (void)in_sizes; (void)n_in; (void)out_size;
}

// round 13
// speedup vs baseline: 1.6200x; 1.1345x over previous
#include <cuda_runtime.h>
#include <cuda_fp16.h>
#include <cstdint>

// ---------------- problem constants ----------------
#define HD   256      // hidden / embedding dim
#define G3   768      // 3*H gate dim
#define VOCAB 30000
#define NW   2048     // word-level sequences (B*R*S)
#define TW   32       // word-level timesteps (W)
#define NS   128      // sentence-level sequences (B*R)
#define TS   16       // sentence-level timesteps (S)
#define NR   8        // review-level sequences (B)
#define TR   16       // review-level timesteps (R)

#define WH   264      // Wres row stride in halfs (528B -> conflict-free ldsm)
#define HS2  40       // H/A/B chunk row stride in halfs (80B -> conflict-free ldsm)

// scan smem (halfs): Wres[96*WH] + Hsm[2][128][HS2]
#define SCAN_SMEM_BYTES ((96*WH + 2*128*HS2) * 2)
// gemm smem (halfs): As[2][128][HS2] + Bs[2][64][HS2]
#define GEMM_SMEM_BYTES ((2*128*HS2 + 2*64*HS2) * 2)

#define NBAR 36       // word 0..31, sentence 32..33, review 34..35
#define BPAD 32       // barrier slot padding (128B)

// ---------------- scratch (static device globals; no runtime alloc) ----------------
__device__ __half g_PV [(size_t)2*VOCAB*G3];       // projected vocab per dir (fp16)
__device__ __half g_GXs[(size_t)2*NS*TS*G3];       // sentence-level gx (fp16)
__device__ __half g_GXr[(size_t)2*NR*TR*G3];       // review-level gx (fp16)
__device__ float  g_Hw [2][(size_t)2*NW*HD];       // ping-pong hidden, word
__device__ float  g_Hs [2][(size_t)2*NS*HD];       // sentence
__device__ float  g_Hr [2][(size_t)2*NR*HD];       // review

// grid-barrier state: one padded slot per (scan, dir, rowgroup)
__device__ unsigned g_cnt[NBAR * BPAD];
__device__ volatile unsigned g_phase[NBAR * BPAD];

// ---------------- helpers ----------------
__device__ __forceinline__ float fsigm(float x) {
    float e = __expf(-x);
    return __fdividef(1.f, 1.f + e);
}
__device__ __forceinline__ float ftanh(float x) {
    float ax = fabsf(x);
    float e = __expf(-2.f * ax);
    float r = __fdividef(1.f - e, 1.f + e);
    return copysignf(r, x);
}

__device__ __forceinline__ unsigned f2h2u(float lo, float hi) {
    __half2 h = __floats2half2_rn(lo, hi);
    return *(unsigned*)&h;
}

__device__ __forceinline__ void mma16(float* d,
                                      unsigned a0, unsigned a1, unsigned a2, unsigned a3,
                                      unsigned b0, unsigned b1) {
    asm volatile(
        "mma.sync.aligned.m16n8k16.row.col.f32.f16.f16.f32 "
        "{%0,%1,%2,%3},{%4,%5,%6,%7},{%8,%9},{%0,%1,%2,%3};"
        : "+f"(d[0]), "+f"(d[1]), "+f"(d[2]), "+f"(d[3])
        : "r"(a0), "r"(a1), "r"(a2), "r"(a3), "r"(b0), "r"(b1));
}

__device__ __forceinline__ void ldsm4(unsigned& r0, unsigned& r1, unsigned& r2, unsigned& r3,
                                      unsigned addr) {
    asm volatile("ldmatrix.sync.aligned.m8n8.x4.shared.b16 {%0,%1,%2,%3}, [%4];"
                 : "=r"(r0), "=r"(r1), "=r"(r2), "=r"(r3) : "r"(addr));
}
__device__ __forceinline__ void ldsm2(unsigned& r0, unsigned& r1, unsigned addr) {
    asm volatile("ldmatrix.sync.aligned.m8n8.x2.shared.b16 {%0,%1}, [%2];"
                 : "=r"(r0), "=r"(r1) : "r"(addr));
}

// named barrier over 128 threads (4 warps), ids 1..2
__device__ __forceinline__ void barhalf(int id) {
    asm volatile("bar.sync %0, 128;" :: "r"(id) : "memory");
}

__global__ void kinit_bar() {
    for (int i = threadIdx.x; i < NBAR * BPAD; i += blockDim.x) {
        g_cnt[i] = 0; g_phase[i] = 0;
    }
}

// software grid barrier over an nCTA-member group (slot = id*BPAD)
__device__ __forceinline__ void gbar(int id, unsigned nCTA, unsigned target) {
    __syncthreads();
    if (threadIdx.x == 0) {
        __threadfence();
        unsigned* cnt = &g_cnt[id * BPAD];
        unsigned old = atomicAdd(cnt, 1u);
        if (old == nCTA - 1u) {
            *cnt = 0u;
            __threadfence();
            g_phase[id * BPAD] = target;
        } else {
            while (g_phase[id * BPAD] < target) __nanosleep(32);
        }
        __threadfence();
    }
    __syncthreads();
}

// ---------------- FP16 GEMM: C[d][M,768] = (A(+A2))[M,256] @ W[d][768,256]^T + bias[d] ----------------
// Output written as fp16. CTA 128(m) x 64(n), warps 4m x 2n, warp tile 32x32.
__global__ __launch_bounds__(256, 2)
void gemm_proj_mma(const float* __restrict__ A, const float* __restrict__ A2, int M,
                   const float* __restrict__ W, const float* __restrict__ bias,
                   __half* __restrict__ C)
{
    extern __shared__ __half gsm[];
    __half* As = gsm;                   // [2][128][HS2]
    __half* Bs = gsm + 2 * 128 * HS2;   // [2][64][HS2]

    int d = blockIdx.z;
    const float* Wd = W    + (size_t)d * G3 * HD;
    const float* bd = bias + (size_t)d * G3;
    __half*      Cd = C    + (size_t)d * M * G3;

    int m0 = blockIdx.x * 128;
    int n0 = blockIdx.y * 64;

    int tid = threadIdx.x, lane = tid & 31, wid = tid >> 5;
    int wm = wid & 3, wn = wid >> 2;
    int RB = wm * 32, CB = wn * 32;
    int g = lane >> 2, c = lane & 3;

    int l7 = lane & 7, ts = lane >> 3;
    unsigned sAs = (unsigned)__cvta_generic_to_shared(As);
    unsigned sBs = (unsigned)__cvta_generic_to_shared(Bs);

    unsigned aAddr[2];
#pragma unroll
    for (int mt = 0; mt < 2; ++mt)
        aAddr[mt] = sAs + (unsigned)(((RB + mt * 16 + l7 + (ts & 1) * 8) * HS2
                                      + (ts >> 1) * 8) * 2);
    unsigned bAddr[2];
#pragma unroll
    for (int p = 0; p < 2; ++p)
        bAddr[p] = sBs + (unsigned)(((CB + (2 * p + (ts >> 1)) * 8 + l7) * HS2
                                     + (ts & 1) * 8) * 2);

    float acc[2][4][4];
#pragma unroll
    for (int i = 0; i < 2; ++i)
#pragma unroll
        for (int j = 0; j < 4; ++j)
#pragma unroll
            for (int k = 0; k < 4; ++k) acc[i][j][k] = 0.f;

    int lr = tid >> 3, lq = tid & 7;

    float4 pa[4], pw[2];
#pragma unroll
    for (int it = 0; it < 4; ++it) {
        int r = lr + it * 32;
        pa[it] = make_float4(0.f, 0.f, 0.f, 0.f);
        if (m0 + r < M) {
            size_t off = (size_t)(m0 + r) * HD + lq * 4;
            pa[it] = *(const float4*)(A + off);
            if (A2) {
                float4 b = *(const float4*)(A2 + off);
                pa[it].x += b.x; pa[it].y += b.y; pa[it].z += b.z; pa[it].w += b.w;
            }
        }
    }
#pragma unroll
    for (int it = 0; it < 2; ++it) {
        int r = lr + it * 32;
        pw[it] = *(const float4*)(Wd + (size_t)(n0 + r) * HD + lq * 4);
    }
#pragma unroll
    for (int it = 0; it < 4; ++it) {
        int r = lr + it * 32;
        *(uint2*)(As + (size_t)r * HS2 + lq * 4) =
            make_uint2(f2h2u(pa[it].x, pa[it].y), f2h2u(pa[it].z, pa[it].w));
    }
#pragma unroll
    for (int it = 0; it < 2; ++it) {
        int r = lr + it * 32;
        *(uint2*)(Bs + (size_t)r * HS2 + lq * 4) =
            make_uint2(f2h2u(pw[it].x, pw[it].y), f2h2u(pw[it].z, pw[it].w));
    }
    __syncthreads();

    for (int k0i = 0; k0i < 8; ++k0i) {
        int cur = k0i & 1;
        if (k0i < 7) {
            int k0 = (k0i + 1) * 32;
#pragma unroll
            for (int it = 0; it < 4; ++it) {
                int r = lr + it * 32;
                pa[it] = make_float4(0.f, 0.f, 0.f, 0.f);
                if (m0 + r < M) {
                    size_t off = (size_t)(m0 + r) * HD + k0 + lq * 4;
                    pa[it] = *(const float4*)(A + off);
                    if (A2) {
                        float4 b = *(const float4*)(A2 + off);
                        pa[it].x += b.x; pa[it].y += b.y; pa[it].z += b.z; pa[it].w += b.w;
                    }
                }
            }
#pragma unroll
            for (int it = 0; it < 2; ++it) {
                int r = lr + it * 32;
                pw[it] = *(const float4*)(Wd + (size_t)(n0 + r) * HD + k0 + lq * 4);
            }
        }

        unsigned aBuf = (unsigned)(cur * 128 * HS2 * 2);
        unsigned bBuf = (unsigned)(cur * 64 * HS2 * 2);
#pragma unroll
        for (int ks = 0; ks < 2; ++ks) {
            unsigned kbo = (unsigned)(ks * 32);
            unsigned a[2][4];
#pragma unroll
            for (int mt = 0; mt < 2; ++mt)
                ldsm4(a[mt][0], a[mt][1], a[mt][2], a[mt][3], aAddr[mt] + aBuf + kbo);
            unsigned b[4][2];
#pragma unroll
            for (int p = 0; p < 2; ++p)
                ldsm4(b[2*p][0], b[2*p][1], b[2*p+1][0], b[2*p+1][1], bAddr[p] + bBuf + kbo);
#pragma unroll
            for (int nt = 0; nt < 4; ++nt)
#pragma unroll
                for (int mt = 0; mt < 2; ++mt)
                    mma16(acc[mt][nt], a[mt][0], a[mt][1], a[mt][2], a[mt][3],
                          b[nt][0], b[nt][1]);
        }

        if (k0i < 7) {
            __half* An = As + (size_t)(cur ^ 1) * 128 * HS2;
            __half* Bn = Bs + (size_t)(cur ^ 1) * 64 * HS2;
#pragma unroll
            for (int it = 0; it < 4; ++it) {
                int r = lr + it * 32;
                *(uint2*)(An + (size_t)r * HS2 + lq * 4) =
                    make_uint2(f2h2u(pa[it].x, pa[it].y), f2h2u(pa[it].z, pa[it].w));
            }
#pragma unroll
            for (int it = 0; it < 2; ++it) {
                int r = lr + it * 32;
                *(uint2*)(Bn + (size_t)r * HS2 + lq * 4) =
                    make_uint2(f2h2u(pw[it].x, pw[it].y), f2h2u(pw[it].z, pw[it].w));
            }
        }
        __syncthreads();
    }

#pragma unroll
    for (int nt = 0; nt < 4; ++nt) {
        int col = n0 + CB + nt * 8 + 2 * c;
        float2 bb = *(const float2*)(bd + col);
#pragma unroll
        for (int mt = 0; mt < 2; ++mt) {
            int row0 = m0 + RB + mt * 16 + g;
            if (row0 < M)
                *(__half2*)(Cd + (size_t)row0 * G3 + col) =
                    __floats2half2_rn(acc[mt][nt][0] + bb.x, acc[mt][nt][1] + bb.y);
            int row1 = row0 + 8;
            if (row1 < M)
                *(__half2*)(Cd + (size_t)row1 * G3 + col) =
                    __floats2half2_rn(acc[mt][nt][2] + bb.x, acc[mt][nt][3] + bb.y);
        }
    }
}

// ---------------- persistent fused GRU scan (fp16 MMA, 128x32 tile) ----------------
// CTA: 128 rows x 32 j-cols x 3 gates; warps 2m x 4n (warp tile 64x8x3).
// W resident fp16 (96 rows); H staged fp16 double-buffered, one 4-warp named
// barrier per chunk. Rowgroup grid barrier couples gridDim.y CTAs.
__global__ __launch_bounds__(256, 2)
void gru_scan(float* __restrict__ H0, float* __restrict__ H1,
              const float* __restrict__ Whh,    // [2][768][256]
              const float* __restrict__ bhh,    // [2][768]
              const __half* __restrict__ GX,    // [2][N*T][768] or nullptr
              const __half* __restrict__ PV,    // [2][VOCAB][768] or nullptr
              const int*   __restrict__ tok,    // tokens or nullptr
              int N, int T, int barBase)
{
    extern __shared__ __half smemh[];
    __half* Wres = smemh;                        // [96][WH] rows: gt*32 + j
    __half* Hsm  = smemh + 96 * WH;              // [2][128][HS2]

    int d  = blockIdx.z;
    int n0 = blockIdx.x * 128;
    int j0 = blockIdx.y * 32;
    int bid = barBase + d * gridDim.x + blockIdx.x;

    const float* Wd = Whh + (size_t)d * G3 * HD;

    int tid = threadIdx.x, lane = tid & 31, wid = tid >> 5;
    int wm = wid & 1, wn = wid >> 1;
    int RB = wm * 64, CB = wn * 8;
    int g = lane >> 2, c = lane & 3;

    // ---- load resident W slice (fp16 RN once): 96 rows x 256 cols ----
    for (int idx = tid; idx < 96 * 64; idx += 256) {
        int row = idx >> 6;
        int c4  = idx & 63;
        int gt = row >> 5, j = row & 31;
        float4 v = *(const float4*)(Wd + (size_t)(gt * 256 + j0 + j) * HD + c4 * 4);
        *(uint2*)(Wres + (size_t)row * WH + c4 * 4) =
            make_uint2(f2h2u(v.x, v.y), f2h2u(v.z, v.w));
    }
    __syncthreads();

    int l7 = lane & 7, ts = lane >> 3;
    unsigned sH = (unsigned)__cvta_generic_to_shared(Hsm);
    unsigned sW = (unsigned)__cvta_generic_to_shared(Wres);

    unsigned aAddr[4];
#pragma unroll
    for (int mt = 0; mt < 4; ++mt)
        aAddr[mt] = sH + (unsigned)(((RB + mt * 16 + l7 + (ts & 1) * 8) * HS2
                                     + (ts >> 1) * 8) * 2);
    // gates 0,1 via one ldsm4 (rows gt*32 + CB + l7); gate 2 via ldsm2
    unsigned bAddr01 = sW + (unsigned)((((ts >> 1) * 32 + CB + l7) * WH + (ts & 1) * 8) * 2);
    unsigned bAddr2  = sW + (unsigned)(((64 + CB + l7) * WH + (ts & 1) * 8) * 2);

    bool is64 = false;
    if (tok) is64 = (tok[1] == 0) & (tok[3] == 0) & (tok[5] == 0) & (tok[7] == 0);

    int cc = j0 + CB + 2 * c;
    float2 br2 = *(const float2*)(bhh + (size_t)d * G3 + cc);
    float2 bz2 = *(const float2*)(bhh + (size_t)d * G3 + 256 + cc);
    float2 bn2 = *(const float2*)(bhh + (size_t)d * G3 + 512 + cc);

    // slab staging: 4 warps of group wm stage rows [wm*64, +64), 4 iters of 16 rows
    int gid = wn * 32 + lane;                 // 0..127 within wm-group
    int srow0 = wm * 64 + (gid >> 3);         // + it*16
    int sq = gid & 7;
    int barId = wm + 1;

    int rowi[8];
#pragma unroll
    for (int idx = 0; idx < 8; ++idx) {
        int mt = idx >> 1, half = idx & 1;
        rowi[idx] = n0 + RB + mt * 16 + g + half * 8;
    }

    for (int t = 0; t < T; ++t) {
        const float* Hin  = (t & 1) ? H1 : H0;
        float*       Hout = (t & 1) ? H0 : H1;
        int teff = d ? (T - 1 - t) : t;

        const __half* gxp[8];
#pragma unroll
        for (int idx = 0; idx < 8; ++idx) {
            int r = rowi[idx];
            if (r < N) {
                if (tok) {
                    int ti = r * T + teff;
                    int tv = is64 ? tok[2 * (size_t)ti] : tok[ti];
                    gxp[idx] = PV + ((size_t)d * VOCAB + tv) * G3;
                } else {
                    gxp[idx] = GX + ((size_t)d * N * T + (size_t)r * T + teff) * G3;
                }
            } else gxp[idx] = PV ? PV : GX;
        }

        float acc[3][4][4];
#pragma unroll
        for (int i = 0; i < 3; ++i)
#pragma unroll
            for (int j = 0; j < 4; ++j)
#pragma unroll
                for (int k = 0; k < 4; ++k) acc[i][j][k] = 0.f;

        if (t > 0) {   // step 0: Hin == 0 -> Gh == 0
            float4 ph[4];
#pragma unroll
            for (int it = 0; it < 4; ++it) {
                int rl = srow0 + it * 16;
                ph[it] = make_float4(0.f, 0.f, 0.f, 0.f);
                if (n0 + rl < N)
                    ph[it] = *(const float4*)(Hin + (size_t)(d * N + n0 + rl) * HD + sq * 4);
            }

            for (int k0i = 0; k0i < 8; ++k0i) {
                __half* buf = Hsm + (size_t)(k0i & 1) * 128 * HS2;
#pragma unroll
                for (int it = 0; it < 4; ++it)
                    *(uint2*)(buf + (size_t)(srow0 + it * 16) * HS2 + sq * 4) =
                        make_uint2(f2h2u(ph[it].x, ph[it].y), f2h2u(ph[it].z, ph[it].w));
                barhalf(barId);

                if (k0i < 7) {
                    int k0 = (k0i + 1) * 32;
#pragma unroll
                    for (int it = 0; it < 4; ++it) {
                        int rl = srow0 + it * 16;
                        ph[it] = make_float4(0.f, 0.f, 0.f, 0.f);
                        if (n0 + rl < N)
                            ph[it] = *(const float4*)(Hin + (size_t)(d * N + n0 + rl) * HD + k0 + sq * 4);
                    }
                }

                unsigned hbuf = (unsigned)((k0i & 1) * 128 * HS2 * 2);
                unsigned kwo  = (unsigned)(k0i * 64);   // 32 halfs per chunk in W
#pragma unroll
                for (int ks = 0; ks < 2; ++ks) {
                    unsigned kbo = (unsigned)(ks * 32); // 16 halfs
                    unsigned a[4][4];
#pragma unroll
                    for (int mt = 0; mt < 4; ++mt)
                        ldsm4(a[mt][0], a[mt][1], a[mt][2], a[mt][3],
                              aAddr[mt] + hbuf + kbo);
                    unsigned b00, b01, b10, b11, b20, b21;
                    ldsm4(b00, b01, b10, b11, bAddr01 + kwo + kbo);
                    ldsm2(b20, b21, bAddr2 + kwo + kbo);
#pragma unroll
                    for (int mt = 0; mt < 4; ++mt) {
                        mma16(acc[0][mt], a[mt][0], a[mt][1], a[mt][2], a[mt][3], b00, b01);
                        mma16(acc[1][mt], a[mt][0], a[mt][1], a[mt][2], a[mt][3], b10, b11);
                        mma16(acc[2][mt], a[mt][0], a[mt][1], a[mt][2], a[mt][3], b20, b21);
                    }
                }
            }
        }

        // ---- gate math epilogue: 8 instances in 2 phases of 4 ----
#pragma unroll
        for (int phx = 0; phx < 2; ++phx) {
            float2 GR[4], GZ[4], GN[4], HH[4];
            bool val[4];
#pragma unroll
            for (int i = 0; i < 4; ++i) {
                int idx = phx * 4 + i;
                int r = rowi[idx];
                val[i] = (r < N);
                GR[i] = GZ[i] = GN[i] = HH[i] = make_float2(0.f, 0.f);
                if (val[i]) {
                    const __half* gxrow = gxp[idx];
                    GR[i] = __half22float2(*(const __half2*)(gxrow + cc));
                    GZ[i] = __half22float2(*(const __half2*)(gxrow + 256 + cc));
                    GN[i] = __half22float2(*(const __half2*)(gxrow + 512 + cc));
                    if (t > 0) HH[i] = *(const float2*)(Hin + (size_t)(d * N + r) * HD + cc);
                }
            }
#pragma unroll
            for (int i = 0; i < 4; ++i) {
                if (!val[i]) continue;
                int idx = phx * 4 + i;
                int mt = idx >> 1, half = idx & 1;
                float aR0 = acc[0][mt][half * 2 + 0], aR1 = acc[0][mt][half * 2 + 1];
                float aZ0 = acc[1][mt][half * 2 + 0], aZ1 = acc[1][mt][half * 2 + 1];
                float aN0 = acc[2][mt][half * 2 + 0], aN1 = acc[2][mt][half * 2 + 1];

                float r0 = fsigm(GR[i].x + aR0 + br2.x);
                float r1 = fsigm(GR[i].y + aR1 + br2.y);
                float z0 = fsigm(GZ[i].x + aZ0 + bz2.x);
                float z1 = fsigm(GZ[i].y + aZ1 + bz2.y);
                float n0v = ftanh(GN[i].x + r0 * (aN0 + bn2.x));
                float n1v = ftanh(GN[i].y + r1 * (aN1 + bn2.y));

                float2 o;
                o.x = n0v + z0 * (HH[i].x - n0v);
                o.y = n1v + z1 * (HH[i].y - n1v);
                *(float2*)(Hout + (size_t)(d * N + rowi[idx]) * HD + cc) = o;
            }
        }

        if (t + 1 < T) gbar(bid, gridDim.y, (unsigned)(t + 1));
    }
}

// ---------------- FC head: Linear(256->128) -> SELU -> Linear(128->1) on (X+X2) ----------------
__global__ void fc_head(const float* __restrict__ X, const float* __restrict__ X2,
                        const float* __restrict__ W1, const float* __restrict__ b1,
                        const float* __restrict__ W2, const float* __restrict__ b2,
                        float* __restrict__ out)
{
    int row = blockIdx.x;
    int h = threadIdx.x;  // 128 threads
    const float* x  = X  + (size_t)row * HD;
    const float* x2 = X2 + (size_t)row * HD;
    const float* w  = W1 + (size_t)h * HD;
    float s = 0.f;
#pragma unroll 8
    for (int k = 0; k < HD; k += 4) {
        float4 xv = *(const float4*)(x + k);
        float4 yv = *(const float4*)(x2 + k);
        float4 wv = *(const float4*)(w + k);
        s += (xv.x + yv.x) * wv.x + (xv.y + yv.y) * wv.y
           + (xv.z + yv.z) * wv.z + (xv.w + yv.w) * wv.w;
    }
    s += b1[h];
    const float SC = 1.0507009873554805f, AL = 1.6732632423543772f;
    float selu = SC * (s > 0.f ? s : AL * expm1f(s));
    float v = selu * W2[h];
    __shared__ float red[128];
    red[h] = v; __syncthreads();
    for (int st = 64; st > 0; st >>= 1) {
        if (h < st) red[h] += red[h + st];
        __syncthreads();
    }
    if (h == 0) out[row] = red[0] + b2[0];
}

// ---------------- launch ----------------
extern "C" void kernel_launch(void* const* d_in, const int* in_sizes, int n_in,
                              void* d_out, int out_size)
{
    const int*   tok   = (const int*)  d_in[0];
    const float* emb   = (const float*)d_in[1];
    const float* wWih  = (const float*)d_in[2];
    const float* wWhh  = (const float*)d_in[3];
    const float* wbih  = (const float*)d_in[4];
    const float* wbhh  = (const float*)d_in[5];
    const float* sWih  = (const float*)d_in[6];
    const float* sWhh  = (const float*)d_in[7];
    const float* sbih  = (const float*)d_in[8];
    const float* sbhh  = (const float*)d_in[9];
    const float* rWih  = (const float*)d_in[10];
    const float* rWhh  = (const float*)d_in[11];
    const float* rbih  = (const float*)d_in[12];
    const float* rbhh  = (const float*)d_in[13];
    const float* rfcW1 = (const float*)d_in[14];
    const float* rfcb1 = (const float*)d_in[15];
    const float* rfcW2 = (const float*)d_in[16];
    const float* rfcb2 = (const float*)d_in[17];
    const float* pfcW1 = (const float*)d_in[18];
    const float* pfcb1 = (const float*)d_in[19];
    const float* pfcW2 = (const float*)d_in[20];
    const float* pfcb2 = (const float*)d_in[21];
    float* out = (float*)d_out;

    static bool attr_set = false;
    if (!attr_set) {
        cudaFuncSetAttribute(gru_scan, cudaFuncAttributeMaxDynamicSharedMemorySize,
                             SCAN_SMEM_BYTES);
        cudaFuncSetAttribute(gemm_proj_mma, cudaFuncAttributeMaxDynamicSharedMemorySize,
                             GEMM_SMEM_BYTES);
        attr_set = true;
    }

    __half *pv, *gxs, *gxr;
    float *hwB, *hsB, *hrB;
    cudaGetSymbolAddress((void**)&pv,  g_PV);
    cudaGetSymbolAddress((void**)&gxs, g_GXs);
    cudaGetSymbolAddress((void**)&gxr, g_GXr);
    cudaGetSymbolAddress((void**)&hwB, g_Hw);
    cudaGetSymbolAddress((void**)&hsB, g_Hs);
    cudaGetSymbolAddress((void**)&hrB, g_Hr);

    float* hw1 = hwB + (size_t)2 * NW * HD;
    float* hs1 = hsB + (size_t)2 * NS * HD;
    float* hr1 = hrB + (size_t)2 * NR * HD;

    kinit_bar<<<1, 1024>>>();

    // project full vocabulary once per direction: PV = emb @ Wih^T + bih (fp16 out)
    gemm_proj_mma<<<dim3((VOCAB + 127) / 128, G3 / 64, 2), 256, GEMM_SMEM_BYTES>>>(
        emb, nullptr, VOCAB, wWih, wbih, pv);

    // word-level scan (T=32): grid (16, 8, 2), rowgroup barriers of 8 CTAs
    gru_scan<<<dim3(NW / 128, 8, 2), 256, SCAN_SMEM_BYTES>>>(
        hwB, hw1, wWhh, wbhh, nullptr, pv, tok, NW, TW, 0);
    float* hwF = (TW & 1) ? hw1 : hwB;

    // sentence-level: project (hf+hb fused) + scan (T=16)
    gemm_proj_mma<<<dim3((NW + 127) / 128, G3 / 64, 2), 256, GEMM_SMEM_BYTES>>>(
        hwF, hwF + (size_t)NW * HD, NW, sWih, sbih, gxs);
    gru_scan<<<dim3(1, 8, 2), 256, SCAN_SMEM_BYTES>>>(
        hsB, hs1, sWhh, sbhh, gxs, nullptr, nullptr, NS, TS, 32);
    float* hsF = (TS & 1) ? hs1 : hsB;

    // review-star head -> out[8..135]
    fc_head<<<NS, 128>>>(hsF, hsF + (size_t)NS * HD, rfcW1, rfcb1, rfcW2, rfcb2, out + NR);

    // review-level (business) biGRU: project (fused sum) + scan (T=16)
    gemm_proj_mma<<<dim3(1, G3 / 64, 2), 256, GEMM_SMEM_BYTES>>>(
        hsF, hsF + (size_t)NS * HD, NS, rWih, rbih, gxr);
    gru_scan<<<dim3(1, 8, 2), 256, SCAN_SMEM_BYTES>>>(
        hrB, hr1, rWhh, rbhh, gxr, nullptr, nullptr, NR, TR, 34);
    float* hrF = (TR & 1) ? hr1 : hrB;

    // business head -> out[0..7]
    fc_head<<<NR, 128>>>(hrF, hrF + (size_t)NR * HD, pfcW1, pfcb1, pfcW2, pfcb2, out);

    (void)in_sizes; (void)n_in; (void)out_size;
}